// round 12
// baseline (speedup 1.0000x reference)
#include <cuda_runtime.h>
#include <cuda_fp16.h>
#include <cstdint>

// ---------------- problem constants ----------------
#define BATCH 2
#define NPOS  8000          // 20*20*20
#define NQT   63            // ceil(8000/128); tail tile has exactly 64 keys

// -------- device scratch (K8/Vt padded: tail cp.async reads to row 8063) ----
__device__ unsigned char g_Q8[BATCH * NPOS * 64];          // (b,n,k) e4m3, x(0.125*log2e*16)
__device__ unsigned char g_K8[BATCH * NPOS * 64 + 8192];   // (b,n,k) e4m3, x8
__device__ __half        g_Vt[BATCH * 64 * NPOS + 8192];   // (b,c,n) f16 transposed
__device__ __half        g_Oh[BATCH * NPOS * 64];          // (b,n,c) f16

#define QSCALE8 (0.125f * 1.44269504f * 16.0f)   // folded into Wq/bq
#define KSCALE8 8.0f                             // folded into Wk/bk
#define H2_2M7  0x20002000u                      // f16x2 {2^-7, 2^-7}

// ---------------- PTX helpers ----------------
__device__ __forceinline__ uint32_t smem_u32(const void* p) {
    uint32_t a;
    asm("{ .reg .u64 t; cvta.to.shared.u64 t, %1; cvt.u32.u64 %0, t; }"
        : "=r"(a) : "l"(p));
    return a;
}

__device__ __forceinline__ void mma_f16(float d[4], const uint32_t a[4],
                                        const uint32_t b0, const uint32_t b1,
                                        const float c[4]) {
    asm volatile(
        "mma.sync.aligned.m16n8k16.row.col.f32.f16.f16.f32 "
        "{%0,%1,%2,%3}, {%4,%5,%6,%7}, {%8,%9}, {%10,%11,%12,%13};"
        : "=f"(d[0]), "=f"(d[1]), "=f"(d[2]), "=f"(d[3])
        : "r"(a[0]), "r"(a[1]), "r"(a[2]), "r"(a[3]),
          "r"(b0), "r"(b1),
          "f"(c[0]), "f"(c[1]), "f"(c[2]), "f"(c[3]));
}

// fp8 e4m3 mma, k=32, f32 accumulate (sm_89+ PTX)
__device__ __forceinline__ void mma_fp8(float d[4], const uint32_t a[4],
                                        uint32_t b0, uint32_t b1) {
    asm volatile(
        "mma.sync.aligned.m16n8k32.row.col.f32.e4m3.e4m3.f32 "
        "{%0,%1,%2,%3}, {%4,%5,%6,%7}, {%8,%9}, {%0,%1,%2,%3};"
        : "+f"(d[0]), "+f"(d[1]), "+f"(d[2]), "+f"(d[3])
        : "r"(a[0]), "r"(a[1]), "r"(a[2]), "r"(a[3]), "r"(b0), "r"(b1));
}

__device__ __forceinline__ void ldsm4(uint32_t& d0, uint32_t& d1,
                                      uint32_t& d2, uint32_t& d3, uint32_t addr) {
    asm volatile("ldmatrix.sync.aligned.m8n8.x4.shared.b16 {%0,%1,%2,%3}, [%4];"
                 : "=r"(d0), "=r"(d1), "=r"(d2), "=r"(d3) : "r"(addr));
}

// pack (lo, hi) -> f16x2, multiply by 2^-7 (undo fp8 scale), 2^x per lane
__device__ __forceinline__ uint32_t expscale(float lo, float hi) {
    uint32_t h, m, r;
    asm("cvt.rn.f16x2.f32 %0, %1, %2;" : "=r"(h) : "f"(hi), "f"(lo));
    asm("mul.f16x2 %0, %1, %2;" : "=r"(m) : "r"(h), "r"(H2_2M7));
    asm("ex2.approx.f16x2 %0, %1;" : "=r"(r) : "r"(m));
    return r;
}

// f32 -> e4m3 byte. OR of both result bytes hedges the cvt operand-order
// convention: the unused slot converts 0.0f -> 0x00, so OR yields the value
// regardless of which half it lands in.
__device__ __forceinline__ uint32_t f2e4m3(float x) {
    uint16_t r;
    asm("cvt.rn.satfinite.e4m3x2.f32 %0, %1, %2;" : "=h"(r) : "f"(0.f), "f"(x));
    return (uint32_t)((r & 0xFFu) | (r >> 8));
}

__device__ __forceinline__ void cpasync16(uint32_t dst, const void* src) {
    asm volatile("cp.async.cg.shared.global [%0], [%1], 16;" :: "r"(dst), "l"(src));
}
#define CP_COMMIT() asm volatile("cp.async.commit_group;" ::: "memory")

// ============================================================================
// Kernel A: fused QKV projection via mma.sync f16 -> Q8/K8 e4m3, V f16.
//   CTA = 64 positions, 128 threads, grid (125, 2). No tail (8000%64==0).
//   smem words: ws[192*36] | xs[64*36] | q8st[64*20] | k8st[64*20]
//               | vst[64*36] | bs[192]
// ============================================================================
#define WS_OFF   0
#define XS_OFF   6912
#define Q8ST_OFF 9216
#define K8ST_OFF 10496
#define VST_OFF  11776
#define BS_OFF   14080
#define QKV_SMEM_BYTES ((14080 + 192) * 4)   // 57,088 B -> 3 CTAs/SM

__global__ __launch_bounds__(128, 3) void qkv_kernel(
    const float* __restrict__ x,
    const float* __restrict__ wq, const float* __restrict__ bq,
    const float* __restrict__ wk, const float* __restrict__ bk,
    const float* __restrict__ wv, const float* __restrict__ bv)
{
    extern __shared__ uint32_t smw[];
    uint32_t* ws  = smw + WS_OFF;                        // [192][36] f16 pairs
    uint32_t* xs  = smw + XS_OFF;                        // [64][36]
    unsigned char* q8st = (unsigned char*)(smw + Q8ST_OFF);  // [64 pos][80 B]
    unsigned char* k8st = (unsigned char*)(smw + K8ST_OFF);  // [64 pos][80 B]
    __half*  vst  = (__half*)(smw + VST_OFF);            // [64 chan][72 pos]
    float*   bs   = (float*)(smw + BS_OFF);              // [192]
    const uint32_t sbase = smem_u32(smw);

    const int tid  = threadIdx.x;
    const int wid  = tid >> 5, lane = tid & 31;
    const int g    = lane >> 2, tig = lane & 3;
    const int b    = blockIdx.y;
    const int n0   = blockIdx.x * 64;
    const int p0   = wid * 16;

    // ---- W fill: stacked [192][64] f16; fp8 scales folded in ----
    for (int i = tid; i < 6144; i += 128) {
        int row = i >> 5, c2 = i & 31;
        const float* wsrc = (row < 64) ? wq : (row < 128) ? wk : wv;
        int r = row & 63;
        float w0 = wsrc[r * 64 + 2 * c2], w1 = wsrc[r * 64 + 2 * c2 + 1];
        if (row < 64)        { w0 *= QSCALE8; w1 *= QSCALE8; }
        else if (row < 128)  { w0 *= KSCALE8; w1 *= KSCALE8; }
        __half2 h = __floats2half2_rn(w0, w1);
        ws[row * 36 + c2] = *(uint32_t*)&h;
    }
    for (int i = tid; i < 192; i += 128) {
        bs[i] = (i < 64) ? bq[i] * QSCALE8
              : (i < 128) ? bk[i - 64] * KSCALE8 : bv[i - 128];
    }
    // ---- x fill: transpose (b,c,n) -> xs[pos][chan] f16 ----
    for (int i = tid; i < 2048; i += 128) {
        int c2 = i >> 6, p = i & 63;
        float x0 = x[(b * 64 + 2 * c2    ) * NPOS + n0 + p];
        float x1 = x[(b * 64 + 2 * c2 + 1) * NPOS + n0 + p];
        __half2 h = __floats2half2_rn(x0, x1);
        xs[p * 36 + c2] = *(uint32_t*)&h;
    }
    __syncthreads();

    // ---- B-fragments: this warp's 16 positions, all 64 k ----
    const int row_in = (lane & 7) | ((lane >> 4) << 3);
    const int woff   = ((lane >> 3) & 1) << 2;
    const uint32_t xLane = sbase + (uint32_t)((XS_OFF + (p0 + row_in) * 36 + woff) * 4);
    uint32_t bfr[4][4];
#pragma unroll
    for (int kk = 0; kk < 4; ++kk)
        ldsm4(bfr[kk][0], bfr[kk][1], bfr[kk][2], bfr[kk][3],
              xLane + (uint32_t)(kk * 32));

    const uint32_t aLaneBase = sbase
        + (uint32_t)(((lane & 15) * 36) * 4) + (uint32_t)(((lane >> 4) << 4));

    const int pA = p0 + 2 * tig;
    const int pB = pA + 8;

#pragma unroll
    for (int mb = 0; mb < 12; ++mb) {
        float d0[4] = {0.f, 0.f, 0.f, 0.f};
        float d1[4] = {0.f, 0.f, 0.f, 0.f};
        const uint32_t aL = aLaneBase + (uint32_t)(mb * 16 * 36 * 4);
#pragma unroll
        for (int kk = 0; kk < 4; ++kk) {
            uint32_t a[4];
            ldsm4(a[0], a[1], a[2], a[3], aL + (uint32_t)(kk * 32));
            mma_f16(d0, a, bfr[kk][0], bfr[kk][1], d0);
            mma_f16(d1, a, bfr[kk][2], bfr[kk][3], d1);
        }
        const int ch0 = mb * 16 + g, ch1 = ch0 + 8;
        const float bb0 = bs[ch0], bb1 = bs[ch1];
        if (mb < 8) {
            unsigned char* st = (mb < 4) ? q8st : k8st;
            const int cc0 = ch0 & 63, cc1 = ch1 & 63;
            st[ pA      * 80 + cc0] = (unsigned char)f2e4m3(d0[0] + bb0);
            st[(pA + 1) * 80 + cc0] = (unsigned char)f2e4m3(d0[1] + bb0);
            st[ pA      * 80 + cc1] = (unsigned char)f2e4m3(d0[2] + bb1);
            st[(pA + 1) * 80 + cc1] = (unsigned char)f2e4m3(d0[3] + bb1);
            st[ pB      * 80 + cc0] = (unsigned char)f2e4m3(d1[0] + bb0);
            st[(pB + 1) * 80 + cc0] = (unsigned char)f2e4m3(d1[1] + bb0);
            st[ pB      * 80 + cc1] = (unsigned char)f2e4m3(d1[2] + bb1);
            st[(pB + 1) * 80 + cc1] = (unsigned char)f2e4m3(d1[3] + bb1);
        } else {
            const int cc0 = ch0 - 128, cc1 = ch1 - 128;
            *(__half2*)&vst[cc0 * 72 + pA] = __floats2half2_rn(d0[0] + bb0, d0[1] + bb0);
            *(__half2*)&vst[cc1 * 72 + pA] = __floats2half2_rn(d0[2] + bb1, d0[3] + bb1);
            *(__half2*)&vst[cc0 * 72 + pB] = __floats2half2_rn(d1[0] + bb0, d1[1] + bb0);
            *(__half2*)&vst[cc1 * 72 + pB] = __floats2half2_rn(d1[2] + bb1, d1[3] + bb1);
        }
    }
    __syncthreads();

    // ---- coalesced copy-out (no guards: 8000 % 64 == 0) ----
    for (int i = tid; i < 256; i += 128) {
        int r = i >> 2, c16 = (i & 3) << 4;
        *(uint4*)&g_Q8[((b * NPOS) + n0 + r) * 64 + c16] =
            *(const uint4*)(q8st + r * 80 + c16);
        *(uint4*)&g_K8[((b * NPOS) + n0 + r) * 64 + c16] =
            *(const uint4*)(k8st + r * 80 + c16);
    }
    for (int i = tid; i < 512; i += 128) {
        int r = i >> 3, p8 = (i & 7) << 3;
        *(uint4*)&g_Vt[((b * 64) + r) * NPOS + n0 + p8] =
            *(const uint4*)&vst[r * 72 + p8];
    }
}

// ============================================================================
// Kernel B: flash attention. S via fp8 e4m3 m16n8k32 (2 mma per 8-key block),
// PV via f16 m16n8k16 (unchanged). exp = pack f16x2 -> x 2^-7 -> ex2.f16x2.
//   smem bytes: Q8[128][80] | K8 x2 stages [128][80] | V x2 stages [64][272]
// ============================================================================
#define VSTW 68                     // V row stride in words (136 f16)
#define Q8_BYTES  (128 * 80)        // 10,240
#define K8_STAGE  (128 * 80)        // 10,240
#define V_STAGE   (64 * VSTW * 4)   // 17,408
#define K8_BASE   Q8_BYTES
#define V_BASE    (K8_BASE + 2 * K8_STAGE)
#define FLASH_SMEM_BYTES (V_BASE + 2 * V_STAGE)   // 65,536

template<int JMAX>
__device__ __forceinline__ void do_tile(const char* kp0, uint32_t vb,
                                        const uint32_t qa8[2][4],
                                        float ofrag[8][4],
                                        float& lsum0, float& lsum1)
{
    // ---- S phase: fp8, 2*JMAX n-blocks x 2 k-chunk mma, f32 accum ----
    float sfa[2 * JMAX][4];
#pragma unroll
    for (int nb = 0; nb < 2 * JMAX; ++nb) {
        sfa[nb][0] = 0.f; sfa[nb][1] = 0.f; sfa[nb][2] = 0.f; sfa[nb][3] = 0.f;
        const char* kp = kp0 + nb * 640;    // 8 keys * 80 B
#pragma unroll
        for (int ch = 0; ch < 2; ++ch) {
            uint32_t b0 = *(const uint32_t*)(kp + 32 * ch);
            uint32_t b1 = *(const uint32_t*)(kp + 32 * ch + 16);
            mma_fp8(sfa[nb], qa8[ch], b0, b1);
        }
    }

    // ---- exp phase: scale by 2^-7 (undo fp8 scale), 2^x, pack f16x2 ----
    uint32_t pa[JMAX][4];
#pragma unroll
    for (int j = 0; j < JMAX; ++j) {
        pa[j][0] = expscale(sfa[2 * j    ][0], sfa[2 * j    ][1]);
        pa[j][1] = expscale(sfa[2 * j    ][2], sfa[2 * j    ][3]);
        pa[j][2] = expscale(sfa[2 * j + 1][0], sfa[2 * j + 1][1]);
        pa[j][3] = expscale(sfa[2 * j + 1][2], sfa[2 * j + 1][3]);
    }

    // ---- row sums via HADD2 on the FMA pipe ----
    {
        __half2 h0 = __floats2half2_rn(0.f, 0.f);
        __half2 h1 = h0;
#pragma unroll
        for (int j = 0; j < JMAX; ++j) {
            h0 = __hadd2(h0, *(const __half2*)&pa[j][0]);
            h0 = __hadd2(h0, *(const __half2*)&pa[j][2]);
            h1 = __hadd2(h1, *(const __half2*)&pa[j][1]);
            h1 = __hadd2(h1, *(const __half2*)&pa[j][3]);
        }
        lsum0 += __low2float(h0) + __high2float(h0);
        lsum1 += __low2float(h1) + __high2float(h1);
    }

    // ---- PV phase: f16 mma, unchanged ----
#pragma unroll
    for (int j = 0; j < JMAX; ++j) {
#pragma unroll
        for (int nb2 = 0; nb2 < 4; ++nb2) {
            uint32_t v0, v1, v2, v3;
            ldsm4(v0, v1, v2, v3, vb + (uint32_t)((nb2 * 16 * VSTW + 8 * j) * 4));
            mma_f16(ofrag[2 * nb2    ], pa[j], v0, v1, ofrag[2 * nb2    ]);
            mma_f16(ofrag[2 * nb2 + 1], pa[j], v2, v3, ofrag[2 * nb2 + 1]);
        }
    }
}

__global__ __launch_bounds__(256, 1) void flash_mma_kernel()
{
    extern __shared__ uint32_t smw[];
    char* smb = (char*)smw;
    const uint32_t sbase = smem_u32(smw);

    const int tid  = threadIdx.x;
    const int wid  = tid >> 5, lane = tid & 31;
    const int g    = lane >> 2, tig = lane & 3;
    const int b    = blockIdx.y;
    const int n0   = blockIdx.x * 128;
    const int qrows = min(128, NPOS - n0);
    const int rb   = wid * 16;

    // ---- Q8 tile fill (once; zero-pad missing rows) ----
    for (int idx = tid; idx < 512; idx += 256) {
        int r = idx >> 2, c16 = (idx & 3) << 4;
        uint4 v = make_uint4(0u, 0u, 0u, 0u);
        if (r < qrows)
            v = *(const uint4*)&g_Q8[((b * NPOS) + n0 + r) * 64 + c16];
        *(uint4*)(smb + r * 80 + c16) = v;
    }
    __syncthreads();

    // ---- Q8 A-fragments (fp8 k32): 2 chunks x 4 regs, loop-invariant ----
    uint32_t qa8[2][4];
#pragma unroll
    for (int ch = 0; ch < 2; ++ch) {
        qa8[ch][0] = *(const uint32_t*)(smb + (rb + g    ) * 80 + 4 * tig + 32 * ch);
        qa8[ch][1] = *(const uint32_t*)(smb + (rb + g + 8) * 80 + 4 * tig + 32 * ch);
        qa8[ch][2] = *(const uint32_t*)(smb + (rb + g    ) * 80 + 4 * tig + 16 + 32 * ch);
        qa8[ch][3] = *(const uint32_t*)(smb + (rb + g + 8) * 80 + 4 * tig + 16 + 32 * ch);
    }

    // per-lane offsets
    const int klane8 = g * 80 + 4 * tig;                    // fp8 B-frag (S)
    const int row_in = (lane & 7) | ((lane >> 4) << 3);     // ldmatrix (V)
    const int woff   = ((lane >> 3) & 1) << 2;
    const uint32_t vLane = (uint32_t)((row_in * VSTW + woff) * 4);

    float ofrag[8][4];
#pragma unroll
    for (int nb = 0; nb < 8; ++nb)
#pragma unroll
        for (int i = 0; i < 4; ++i) ofrag[nb][i] = 0.f;
    float lsum0 = 0.f, lsum1 = 0.f;

    auto fill_async = [&](int t, uint32_t kdst, uint32_t vdst) {
        const int kv0 = t * 128;
#pragma unroll
        for (int i = 0; i < 2; ++i) {                       // K8: 512 x 16B
            int idx = tid + i * 256;
            int r = idx >> 2, c16 = (idx & 3) << 4;
            cpasync16(kdst + (uint32_t)(r * 80 + c16),
                      &g_K8[((size_t)(b * NPOS) + kv0 + r) * 64 + c16]);
        }
#pragma unroll
        for (int i = 0; i < 4; ++i) {                       // V: 1024 x 16B
            int idx = tid + i * 256;
            int c = idx >> 4, k8 = (idx & 15) << 3;
            cpasync16(vdst + (uint32_t)((c * VSTW + (k8 >> 1)) * 4),
                      &g_Vt[((size_t)(b * 64) + c) * NPOS + kv0 + k8]);
        }
    };

    fill_async(0, sbase + K8_BASE, sbase + V_BASE);
    CP_COMMIT();

#pragma unroll 1
    for (int t = 0; t < NQT; ++t) {
        __syncthreads();
        const int cur = t & 1;
        if (t + 1 < NQT) {
            fill_async(t + 1, sbase + K8_BASE + (uint32_t)(((t + 1) & 1) * K8_STAGE),
                              sbase + V_BASE  + (uint32_t)(((t + 1) & 1) * V_STAGE));
            CP_COMMIT();
            asm volatile("cp.async.wait_group 1;" ::: "memory");
        } else {
            asm volatile("cp.async.wait_group 0;" ::: "memory");
        }
        __syncthreads();

        const char*  kp0 = smb + K8_BASE + cur * K8_STAGE + klane8;
        const uint32_t vb = sbase + V_BASE + (uint32_t)(cur * V_STAGE) + vLane;

        if (t * 128 + 128 <= NPOS) do_tile<8>(kp0, vb, qa8, ofrag, lsum0, lsum1);
        else                       do_tile<4>(kp0, vb, qa8, ofrag, lsum0, lsum1);
    }

    // ---- epilogue: reduce row sums over tig lanes, normalize, store f16 ----
    lsum0 += __shfl_xor_sync(0xffffffffu, lsum0, 1);
    lsum0 += __shfl_xor_sync(0xffffffffu, lsum0, 2);
    lsum1 += __shfl_xor_sync(0xffffffffu, lsum1, 1);
    lsum1 += __shfl_xor_sync(0xffffffffu, lsum1, 2);
    const float inv0 = 1.0f / lsum0;
    const float inv1 = 1.0f / lsum1;

    const int r0 = rb + g, r1 = rb + g + 8;
    if (r0 < qrows) {
#pragma unroll
        for (int nb = 0; nb < 8; ++nb)
            *(__half2*)&g_Oh[((b * NPOS) + n0 + r0) * 64 + nb * 8 + 2 * tig]
                = __floats2half2_rn(ofrag[nb][0] * inv0, ofrag[nb][1] * inv0);
    }
    if (r1 < qrows) {
#pragma unroll
        for (int nb = 0; nb < 8; ++nb)
            *(__half2*)&g_Oh[((b * NPOS) + n0 + r1) * 64 + nb * 8 + 2 * tig]
                = __floats2half2_rn(ofrag[nb][2] * inv1, ofrag[nb][3] * inv1);
    }
}

// ============================================================================
// Kernel C: output projection (f16 O gather halves traffic).
//   y[b,o,p] = bo[o] + sum_c wo[o,c] * O[b, c*125 + (p>>6), p&63]
// ============================================================================
__global__ __launch_bounds__(512) void out_proj_kernel(
    float* __restrict__ out,
    const float* __restrict__ wo, const float* __restrict__ bo)
{
    __shared__ float wos[4096];
    __shared__ float os[64 * 68];

    const int tid = threadIdx.x;
    const int b   = blockIdx.y;
    const int bx  = blockIdx.x;

    for (int i = tid; i < 4096; i += 512) wos[i] = wo[i];
    for (int i = tid; i < 4096; i += 512) {
        int c = i >> 6, pl = i & 63;
        os[pl * 68 + c] = __half2float(g_Oh[((b * NPOS) + c * 125 + bx) * 64 + pl]);
    }
    __syncthreads();

    const int pl = tid & 63;
    const int o0 = (tid >> 6) << 3;

    float acc[8];
#pragma unroll
    for (int j = 0; j < 8; ++j) acc[j] = 0.f;

#pragma unroll 8
    for (int c = 0; c < 64; c += 4) {
        float4 xv = *(const float4*)&os[pl * 68 + c];
#pragma unroll
        for (int j = 0; j < 8; ++j) {
            float4 w4 = *(const float4*)&wos[(o0 + j) * 64 + c];
            acc[j] += w4.x * xv.x + w4.y * xv.y + w4.z * xv.z + w4.w * xv.w;
        }
    }
#pragma unroll
    for (int j = 0; j < 8; ++j)
        out[((b * 64) + o0 + j) * NPOS + bx * 64 + pl] = acc[j] + bo[o0 + j];
}

// ============================================================================
extern "C" void kernel_launch(void* const* d_in, const int* in_sizes, int n_in,
                              void* d_out, int out_size)
{
    (void)in_sizes; (void)n_in; (void)out_size;
    const float* x  = (const float*)d_in[0];
    const float* wq = (const float*)d_in[1];
    const float* bq = (const float*)d_in[2];
    const float* wk = (const float*)d_in[3];
    const float* bk = (const float*)d_in[4];
    const float* wv = (const float*)d_in[5];
    const float* bv = (const float*)d_in[6];
    const float* wo = (const float*)d_in[7];
    const float* bo = (const float*)d_in[8];
    float* out = (float*)d_out;

    cudaFuncSetAttribute(qkv_kernel,
                         cudaFuncAttributeMaxDynamicSharedMemorySize, QKV_SMEM_BYTES);
    cudaFuncSetAttribute(flash_mma_kernel,
                         cudaFuncAttributeMaxDynamicSharedMemorySize, FLASH_SMEM_BYTES);

    qkv_kernel<<<dim3(125, BATCH), 128, QKV_SMEM_BYTES>>>(x, wq, bq, wk, bk, wv, bv);
    flash_mma_kernel<<<dim3(NQT, BATCH), 256, FLASH_SMEM_BYTES>>>();
    out_proj_kernel<<<dim3(125, BATCH), 512>>>(out, wo, bo);
}

// round 13
// speedup vs baseline: 1.0971x; 1.0971x over previous
#include <cuda_runtime.h>
#include <cuda_fp16.h>
#include <cstdint>

// ---------------- problem constants ----------------
#define BATCH 2
#define NPOS  8000          // 20*20*20
#define NQT   63            // ceil(8000/128); tail tile has exactly 64 keys
#define NITEMS 500          // warp-items per batch (8000 rows / 16)
#define NCPB   72           // CTAs per batch in flash

// -------- device scratch (padded: tail tile cp.async reads up to row 8063) --
__device__ __half g_Qh[BATCH * NPOS * 64];          // (b, n, k) pre-scaled
__device__ __half g_Kh[BATCH * NPOS * 64 + 8192];   // (b, n, k)
__device__ __half g_Vt[BATCH * 64 * NPOS + 8192];   // (b, c, n) transposed
__device__ float  g_O [BATCH * NPOS * 64];          // (b, n, c) fp32

#define QSCALE (0.125f * 1.44269504f)   // 1/sqrt(64) * log2(e), folded into Wq

// ---------------- PTX helpers ----------------
__device__ __forceinline__ uint32_t smem_u32(const void* p) {
    uint32_t a;
    asm("{ .reg .u64 t; cvta.to.shared.u64 t, %1; cvt.u32.u64 %0, t; }"
        : "=r"(a) : "l"(p));
    return a;
}

__device__ __forceinline__ void mma_f16(float d[4], const uint32_t a[4],
                                        const uint32_t b0, const uint32_t b1,
                                        const float c[4]) {
    asm volatile(
        "mma.sync.aligned.m16n8k16.row.col.f32.f16.f16.f32 "
        "{%0,%1,%2,%3}, {%4,%5,%6,%7}, {%8,%9}, {%10,%11,%12,%13};"
        : "=f"(d[0]), "=f"(d[1]), "=f"(d[2]), "=f"(d[3])
        : "r"(a[0]), "r"(a[1]), "r"(a[2]), "r"(a[3]),
          "r"(b0), "r"(b1),
          "f"(c[0]), "f"(c[1]), "f"(c[2]), "f"(c[3]));
}

__device__ __forceinline__ void mma_f16h(uint32_t d[2], const uint32_t a[4],
                                         const uint32_t b0, const uint32_t b1,
                                         const uint32_t c0, const uint32_t c1) {
    asm volatile(
        "mma.sync.aligned.m16n8k16.row.col.f16.f16.f16.f16 "
        "{%0,%1}, {%2,%3,%4,%5}, {%6,%7}, {%8,%9};"
        : "=r"(d[0]), "=r"(d[1])
        : "r"(a[0]), "r"(a[1]), "r"(a[2]), "r"(a[3]),
          "r"(b0), "r"(b1), "r"(c0), "r"(c1));
}

__device__ __forceinline__ void ldsm4(uint32_t& d0, uint32_t& d1,
                                      uint32_t& d2, uint32_t& d3, uint32_t addr) {
    asm volatile("ldmatrix.sync.aligned.m8n8.x4.shared.b16 {%0,%1,%2,%3}, [%4];"
                 : "=r"(d0), "=r"(d1), "=r"(d2), "=r"(d3) : "r"(addr));
}

__device__ __forceinline__ uint32_t ex2h2(uint32_t h) {
    uint32_t r;
    asm("ex2.approx.f16x2 %0, %1;" : "=r"(r) : "r"(h));
    return r;
}

__device__ __forceinline__ void cpasync16(uint32_t dst, const void* src) {
    asm volatile("cp.async.cg.shared.global [%0], [%1], 16;" :: "r"(dst), "l"(src));
}
#define CP_COMMIT() asm volatile("cp.async.commit_group;" ::: "memory")

// ============================================================================
// Kernel A: fused QKV projection via mma.sync f16 (round-11 version verbatim).
//   CTA = 64 positions, 128 threads, grid (125, 2). No tail (8000%64==0).
// ============================================================================
#define WS_OFF  0
#define XS_OFF  6912
#define QST_OFF 9216
#define KST_OFF 11520
#define VST_OFF 13824
#define BS_OFF  16128
#define QKV_SMEM_BYTES ((16128 + 192) * 4)   // 65,280 B

__global__ __launch_bounds__(128, 3) void qkv_kernel(
    const float* __restrict__ x,
    const float* __restrict__ wq, const float* __restrict__ bq,
    const float* __restrict__ wk, const float* __restrict__ bk,
    const float* __restrict__ wv, const float* __restrict__ bv)
{
    extern __shared__ uint32_t smw[];
    uint32_t* ws  = smw + WS_OFF;               // [192][36] f16 pairs
    uint32_t* xs  = smw + XS_OFF;               // [64][36]
    __half*  qst  = (__half*)(smw + QST_OFF);   // [64][72]
    __half*  kst  = (__half*)(smw + KST_OFF);   // [64][72]
    __half*  vst  = (__half*)(smw + VST_OFF);   // [64 chan][72 pos]
    float*   bs   = (float*)(smw + BS_OFF);     // [192]
    const uint32_t sbase = smem_u32(smw);

    const int tid  = threadIdx.x;
    const int wid  = tid >> 5, lane = tid & 31;
    const int g    = lane >> 2, tig = lane & 3;
    const int b    = blockIdx.y;
    const int n0   = blockIdx.x * 64;
    const int p0   = wid * 16;

    for (int i = tid; i < 6144; i += 128) {
        int row = i >> 5, c2 = i & 31;
        const float* wsrc = (row < 64) ? wq : (row < 128) ? wk : wv;
        int r = row & 63;
        float w0 = wsrc[r * 64 + 2 * c2], w1 = wsrc[r * 64 + 2 * c2 + 1];
        if (row < 64) { w0 *= QSCALE; w1 *= QSCALE; }
        __half2 h = __floats2half2_rn(w0, w1);
        ws[row * 36 + c2] = *(uint32_t*)&h;
    }
    for (int i = tid; i < 192; i += 128) {
        bs[i] = (i < 64) ? bq[i] * QSCALE
              : (i < 128) ? bk[i - 64] : bv[i - 128];
    }
    for (int i = tid; i < 2048; i += 128) {
        int c2 = i >> 6, p = i & 63;
        float x0 = x[(b * 64 + 2 * c2    ) * NPOS + n0 + p];
        float x1 = x[(b * 64 + 2 * c2 + 1) * NPOS + n0 + p];
        __half2 h = __floats2half2_rn(x0, x1);
        xs[p * 36 + c2] = *(uint32_t*)&h;
    }
    __syncthreads();

    const int row_in = (lane & 7) | ((lane >> 4) << 3);
    const int woff   = ((lane >> 3) & 1) << 2;
    const uint32_t xLane = sbase + (uint32_t)((XS_OFF + (p0 + row_in) * 36 + woff) * 4);
    uint32_t bfr[4][4];
#pragma unroll
    for (int kk = 0; kk < 4; ++kk)
        ldsm4(bfr[kk][0], bfr[kk][1], bfr[kk][2], bfr[kk][3],
              xLane + (uint32_t)(kk * 32));

    const uint32_t aLaneBase = sbase
        + (uint32_t)(((lane & 15) * 36) * 4) + (uint32_t)(((lane >> 4) << 4));

    const int pA = p0 + 2 * tig;
    const int pB = pA + 8;

#pragma unroll
    for (int mb = 0; mb < 12; ++mb) {
        float d0[4] = {0.f, 0.f, 0.f, 0.f};
        float d1[4] = {0.f, 0.f, 0.f, 0.f};
        const uint32_t aL = aLaneBase + (uint32_t)(mb * 16 * 36 * 4);
#pragma unroll
        for (int kk = 0; kk < 4; ++kk) {
            uint32_t a[4];
            ldsm4(a[0], a[1], a[2], a[3], aL + (uint32_t)(kk * 32));
            mma_f16(d0, a, bfr[kk][0], bfr[kk][1], d0);
            mma_f16(d1, a, bfr[kk][2], bfr[kk][3], d1);
        }
        const int ch0 = mb * 16 + g, ch1 = ch0 + 8;
        const float bb0 = bs[ch0], bb1 = bs[ch1];
        if (mb < 8) {
            __half* st = (mb < 4) ? qst : kst;
            const int cc0 = ch0 & 63, cc1 = ch1 & 63;
            st[ pA      * 72 + cc0] = __float2half_rn(d0[0] + bb0);
            st[(pA + 1) * 72 + cc0] = __float2half_rn(d0[1] + bb0);
            st[ pA      * 72 + cc1] = __float2half_rn(d0[2] + bb1);
            st[(pA + 1) * 72 + cc1] = __float2half_rn(d0[3] + bb1);
            st[ pB      * 72 + cc0] = __float2half_rn(d1[0] + bb0);
            st[(pB + 1) * 72 + cc0] = __float2half_rn(d1[1] + bb0);
            st[ pB      * 72 + cc1] = __float2half_rn(d1[2] + bb1);
            st[(pB + 1) * 72 + cc1] = __float2half_rn(d1[3] + bb1);
        } else {
            const int cc0 = ch0 - 128, cc1 = ch1 - 128;
            *(__half2*)&vst[cc0 * 72 + pA] = __floats2half2_rn(d0[0] + bb0, d0[1] + bb0);
            *(__half2*)&vst[cc1 * 72 + pA] = __floats2half2_rn(d0[2] + bb1, d0[3] + bb1);
            *(__half2*)&vst[cc0 * 72 + pB] = __floats2half2_rn(d1[0] + bb0, d1[1] + bb0);
            *(__half2*)&vst[cc1 * 72 + pB] = __floats2half2_rn(d1[2] + bb1, d1[3] + bb1);
        }
    }
    __syncthreads();

    for (int i = tid; i < 512; i += 128) {
        int r = i >> 3, c8 = (i & 7) << 3;
        *(uint4*)&g_Qh[((b * NPOS) + n0 + r) * 64 + c8] =
            *(const uint4*)&qst[r * 72 + c8];
        *(uint4*)&g_Kh[((b * NPOS) + n0 + r) * 64 + c8] =
            *(const uint4*)&kst[r * 72 + c8];
    }
    for (int i = tid; i < 512; i += 128) {
        int r = i >> 3, p8 = (i & 7) << 3;
        *(uint4*)&g_Vt[((b * 64) + r) * NPOS + n0 + p8] =
            *(const uint4*)&vst[r * 72 + p8];
    }
}

// ============================================================================
// Kernel B: flash attention, wave-balanced warp-pool.
//   grid 144 CTAs (72 per batch), 256 threads. Warp w of CTA c takes warp-item
//   it = c + 72*w (valid iff it < 500); item = 16 q rows [16*it, 16*it+16).
//   Max 7 active warps/CTA -> per-SM tensor work drops 12.5% vs 8-warp CTAs
//   while K/V tile fills/smem stay shared. Row-independent softmax makes any
//   row->warp assignment exact.
// ============================================================================
#define QSTW 36                 // Q/K row stride in words (72 f16)
#define VSTW 68                 // V row stride in words (136 f16)
#define KTILE_W (128 * QSTW)
#define VTILE_W (64 * VSTW)
#define FLASH_SMEM_BYTES ((128 * QSTW + 2 * KTILE_W + 2 * VTILE_W) * 4)  // 90,112

template<int JMAX>
__device__ __forceinline__ void do_tile(uint32_t kb, uint32_t vb,
                                        const uint32_t qa[4][4],
                                        float ofrag[8][4],
                                        float& lsum0, float& lsum1)
{
    // ---- S phase ----
    uint32_t sfh[2 * JMAX][2];
#pragma unroll
    for (int nb = 0; nb < 2 * JMAX; ++nb) { sfh[nb][0] = 0u; sfh[nb][1] = 0u; }
#pragma unroll
    for (int k = 0; k < 4; ++k) {
#pragma unroll
        for (int j = 0; j < JMAX; ++j) {
            uint32_t d0, d1, d2, d3;
            ldsm4(d0, d1, d2, d3, kb + (uint32_t)((j * 16 * QSTW + 8 * k) * 4));
            mma_f16h(sfh[2 * j    ], qa[k], d0, d1, sfh[2 * j    ][0], sfh[2 * j    ][1]);
            mma_f16h(sfh[2 * j + 1], qa[k], d2, d3, sfh[2 * j + 1][0], sfh[2 * j + 1][1]);
        }
    }

    // ---- exp phase ----
    uint32_t pa[JMAX][4];
#pragma unroll
    for (int j = 0; j < JMAX; ++j) {
        pa[j][0] = ex2h2(sfh[2 * j    ][0]);
        pa[j][1] = ex2h2(sfh[2 * j    ][1]);
        pa[j][2] = ex2h2(sfh[2 * j + 1][0]);
        pa[j][3] = ex2h2(sfh[2 * j + 1][1]);
    }

    // ---- row sums via HADD2 on the FMA pipe ----
    {
        __half2 h0 = __floats2half2_rn(0.f, 0.f);
        __half2 h1 = h0;
#pragma unroll
        for (int j = 0; j < JMAX; ++j) {
            h0 = __hadd2(h0, *(const __half2*)&pa[j][0]);
            h0 = __hadd2(h0, *(const __half2*)&pa[j][2]);
            h1 = __hadd2(h1, *(const __half2*)&pa[j][1]);
            h1 = __hadd2(h1, *(const __half2*)&pa[j][3]);
        }
        lsum0 += __low2float(h0) + __high2float(h0);
        lsum1 += __low2float(h1) + __high2float(h1);
    }

    // ---- PV phase ----
#pragma unroll
    for (int j = 0; j < JMAX; ++j) {
#pragma unroll
        for (int nb2 = 0; nb2 < 4; ++nb2) {
            uint32_t v0, v1, v2, v3;
            ldsm4(v0, v1, v2, v3, vb + (uint32_t)((nb2 * 16 * VSTW + 8 * j) * 4));
            mma_f16(ofrag[2 * nb2    ], pa[j], v0, v1, ofrag[2 * nb2    ]);
            mma_f16(ofrag[2 * nb2 + 1], pa[j], v2, v3, ofrag[2 * nb2 + 1]);
        }
    }
}

__global__ __launch_bounds__(256, 1) void flash_mma_kernel()
{
    extern __shared__ uint32_t smw[];
    uint32_t* Qw = smw;                              // [128][36]
    const uint32_t sbase  = smem_u32(smw);
    const uint32_t kbase0 = sbase + 128 * QSTW * 4;
    const uint32_t vbase0 = kbase0 + 2 * KTILE_W * 4;

    const int tid  = threadIdx.x;
    const int wid  = tid >> 5, lane = tid & 31;
    const int g    = lane >> 2, tig = lane & 3;
    const int b    = blockIdx.x / NCPB;              // batch
    const int c    = blockIdx.x % NCPB;              // CTA index within batch
    const int item = c + NCPB * wid;                 // this warp's row-item
    const bool valid = (item < NITEMS);
    const int rbase = item * 16;                     // global q-row base
    const int rb   = wid * 16;                       // smem Q row base

    // ---- Q fill: each ACTIVE warp stages its own 16 rows ----
    if (valid) {
#pragma unroll
        for (int i = 0; i < 4; ++i) {
            int idx = lane + 32 * i;                 // 128 uint4 per warp
            int rr = idx >> 3, c8 = (idx & 7) << 3;
            uint4 v = *(const uint4*)&g_Qh[((b * NPOS) + rbase + rr) * 64 + c8];
            *(uint4*)&Qw[(rb + rr) * QSTW + (c8 >> 1)] = v;
        }
    }
    __syncthreads();

    uint32_t qa[4][4];
#pragma unroll
    for (int k = 0; k < 4; ++k) {
        qa[k][0] = Qw[(rb + g    ) * QSTW + 8 * k + tig];
        qa[k][1] = Qw[(rb + g + 8) * QSTW + 8 * k + tig];
        qa[k][2] = Qw[(rb + g    ) * QSTW + 8 * k + tig + 4];
        qa[k][3] = Qw[(rb + g + 8) * QSTW + 8 * k + tig + 4];
    }

    const int row_in = (lane & 7) | ((lane >> 4) << 3);
    const int woff   = ((lane >> 3) & 1) << 2;
    const uint32_t kLane = (uint32_t)((row_in * QSTW + woff) * 4);
    const uint32_t vLane = (uint32_t)((row_in * VSTW + woff) * 4);

    float ofrag[8][4];
#pragma unroll
    for (int nb = 0; nb < 8; ++nb)
#pragma unroll
        for (int i = 0; i < 4; ++i) ofrag[nb][i] = 0.f;
    float lsum0 = 0.f, lsum1 = 0.f;

    auto fill_async = [&](int t, uint32_t kb, uint32_t vb) {
        const int kv0 = t * 128;
#pragma unroll
        for (int i = 0; i < 4; ++i) {
            int idx = tid + i * 256;
            int r = idx >> 3, c8 = (idx & 7) << 3;
            cpasync16(kb + (uint32_t)((r * QSTW + (c8 >> 1)) * 4),
                      &g_Kh[((size_t)(b * NPOS) + kv0 + r) * 64 + c8]);
        }
#pragma unroll
        for (int i = 0; i < 4; ++i) {
            int idx = tid + i * 256;
            int cc = idx >> 4, k8 = (idx & 15) << 3;
            cpasync16(vb + (uint32_t)((cc * VSTW + (k8 >> 1)) * 4),
                      &g_Vt[((size_t)(b * 64) + cc) * NPOS + kv0 + k8]);
        }
    };

    fill_async(0, kbase0, vbase0);
    CP_COMMIT();

#pragma unroll 1
    for (int t = 0; t < NQT; ++t) {
        __syncthreads();
        const int cur = t & 1;
        if (t + 1 < NQT) {
            fill_async(t + 1, kbase0 + (uint32_t)(((t + 1) & 1) * KTILE_W * 4),
                              vbase0 + (uint32_t)(((t + 1) & 1) * VTILE_W * 4));
            CP_COMMIT();
            asm volatile("cp.async.wait_group 1;" ::: "memory");
        } else {
            asm volatile("cp.async.wait_group 0;" ::: "memory");
        }
        __syncthreads();

        if (!valid) continue;           // idle warps still did fills + syncs

        const uint32_t kb = kbase0 + (uint32_t)(cur * KTILE_W * 4) + kLane;
        const uint32_t vb = vbase0 + (uint32_t)(cur * VTILE_W * 4) + vLane;

        if (t * 128 + 128 <= NPOS) do_tile<8>(kb, vb, qa, ofrag, lsum0, lsum1);
        else                       do_tile<4>(kb, vb, qa, ofrag, lsum0, lsum1);
    }

    if (!valid) return;

    // ---- epilogue: reduce row sums over the 4 tig lanes, normalize, store ----
    lsum0 += __shfl_xor_sync(0xffffffffu, lsum0, 1);
    lsum0 += __shfl_xor_sync(0xffffffffu, lsum0, 2);
    lsum1 += __shfl_xor_sync(0xffffffffu, lsum1, 1);
    lsum1 += __shfl_xor_sync(0xffffffffu, lsum1, 2);
    const float inv0 = 1.0f / lsum0;
    const float inv1 = 1.0f / lsum1;

    const int r0 = rbase + g, r1 = rbase + g + 8;    // always < NPOS when valid
#pragma unroll
    for (int nb = 0; nb < 8; ++nb) {
        *(float2*)&g_O[((b * NPOS) + r0) * 64 + nb * 8 + 2 * tig]
            = make_float2(ofrag[nb][0] * inv0, ofrag[nb][1] * inv0);
        *(float2*)&g_O[((b * NPOS) + r1) * 64 + nb * 8 + 2 * tig]
            = make_float2(ofrag[nb][2] * inv1, ofrag[nb][3] * inv1);
    }
}

// ============================================================================
// Kernel C: output projection, 512 threads (round-11 version verbatim).
//   y[b,o,p] = bo[o] + sum_c wo[o,c] * O[b, c*125 + (p>>6), p&63]
// ============================================================================
__global__ __launch_bounds__(512) void out_proj_kernel(
    float* __restrict__ out,
    const float* __restrict__ wo, const float* __restrict__ bo)
{
    __shared__ float wos[4096];
    __shared__ float os[64 * 68];

    const int tid = threadIdx.x;
    const int b   = blockIdx.y;
    const int bx  = blockIdx.x;

    for (int i = tid; i < 4096; i += 512) wos[i] = wo[i];
    for (int i = tid; i < 4096; i += 512) {
        int c = i >> 6, pl = i & 63;
        os[pl * 68 + c] = g_O[((b * NPOS) + c * 125 + bx) * 64 + pl];
    }
    __syncthreads();

    const int pl = tid & 63;
    const int o0 = (tid >> 6) << 3;

    float acc[8];
#pragma unroll
    for (int j = 0; j < 8; ++j) acc[j] = 0.f;

#pragma unroll 8
    for (int c = 0; c < 64; c += 4) {
        float4 xv = *(const float4*)&os[pl * 68 + c];
#pragma unroll
        for (int j = 0; j < 8; ++j) {
            float4 w4 = *(const float4*)&wos[(o0 + j) * 64 + c];
            acc[j] += w4.x * xv.x + w4.y * xv.y + w4.z * xv.z + w4.w * xv.w;
        }
    }
#pragma unroll
    for (int j = 0; j < 8; ++j)
        out[((b * 64) + o0 + j) * NPOS + bx * 64 + pl] = acc[j] + bo[o0 + j];
}

// ============================================================================
extern "C" void kernel_launch(void* const* d_in, const int* in_sizes, int n_in,
                              void* d_out, int out_size)
{
    (void)in_sizes; (void)n_in; (void)out_size;
    const float* x  = (const float*)d_in[0];
    const float* wq = (const float*)d_in[1];
    const float* bq = (const float*)d_in[2];
    const float* wk = (const float*)d_in[3];
    const float* bk = (const float*)d_in[4];
    const float* wv = (const float*)d_in[5];
    const float* bv = (const float*)d_in[6];
    const float* wo = (const float*)d_in[7];
    const float* bo = (const float*)d_in[8];
    float* out = (float*)d_out;

    cudaFuncSetAttribute(qkv_kernel,
                         cudaFuncAttributeMaxDynamicSharedMemorySize, QKV_SMEM_BYTES);
    cudaFuncSetAttribute(flash_mma_kernel,
                         cudaFuncAttributeMaxDynamicSharedMemorySize, FLASH_SMEM_BYTES);

    qkv_kernel<<<dim3(125, BATCH), 128, QKV_SMEM_BYTES>>>(x, wq, bq, wk, bk, wv, bv);
    flash_mma_kernel<<<BATCH * NCPB, 256, FLASH_SMEM_BYTES>>>();
    out_proj_kernel<<<dim3(125, BATCH), 512>>>(out, wo, bo);
}

// round 14
// speedup vs baseline: 1.1088x; 1.0106x over previous
#include <cuda_runtime.h>
#include <cuda_fp16.h>
#include <cstdint>

// ---------------- problem constants ----------------
#define BATCH 2
#define NPOS  8000          // 20*20*20
#define NKT   32            // kv tiles of 256 keys: 31 full + 1 tail (64 keys)
#define NITEMS 500          // warp-items per batch (8000 rows / 16)
#define NCPB   72           // CTAs per batch in flash

// -------- device scratch (padded: tail fills read K rows/V keys to 8191) ----
__device__ __half g_Qh[BATCH * NPOS * 64];           // (b, n, k) pre-scaled
__device__ __half g_Kh[BATCH * NPOS * 64 + 16384];   // (b, n, k)
__device__ __half g_Vt[BATCH * 64 * NPOS + 16384];   // (b, c, n) transposed
__device__ float  g_O [BATCH * NPOS * 64];           // (b, n, c) fp32

#define QSCALE (0.125f * 1.44269504f)   // 1/sqrt(64) * log2(e), folded into Wq

// ---------------- PTX helpers ----------------
__device__ __forceinline__ uint32_t smem_u32(const void* p) {
    uint32_t a;
    asm("{ .reg .u64 t; cvta.to.shared.u64 t, %1; cvt.u32.u64 %0, t; }"
        : "=r"(a) : "l"(p));
    return a;
}

__device__ __forceinline__ void mma_f16(float d[4], const uint32_t a[4],
                                        const uint32_t b0, const uint32_t b1,
                                        const float c[4]) {
    asm volatile(
        "mma.sync.aligned.m16n8k16.row.col.f32.f16.f16.f32 "
        "{%0,%1,%2,%3}, {%4,%5,%6,%7}, {%8,%9}, {%10,%11,%12,%13};"
        : "=f"(d[0]), "=f"(d[1]), "=f"(d[2]), "=f"(d[3])
        : "r"(a[0]), "r"(a[1]), "r"(a[2]), "r"(a[3]),
          "r"(b0), "r"(b1),
          "f"(c[0]), "f"(c[1]), "f"(c[2]), "f"(c[3]));
}

__device__ __forceinline__ void mma_f16h(uint32_t d[2], const uint32_t a[4],
                                         const uint32_t b0, const uint32_t b1,
                                         const uint32_t c0, const uint32_t c1) {
    asm volatile(
        "mma.sync.aligned.m16n8k16.row.col.f16.f16.f16.f16 "
        "{%0,%1}, {%2,%3,%4,%5}, {%6,%7}, {%8,%9};"
        : "=r"(d[0]), "=r"(d[1])
        : "r"(a[0]), "r"(a[1]), "r"(a[2]), "r"(a[3]),
          "r"(b0), "r"(b1), "r"(c0), "r"(c1));
}

__device__ __forceinline__ void ldsm4(uint32_t& d0, uint32_t& d1,
                                      uint32_t& d2, uint32_t& d3, uint32_t addr) {
    asm volatile("ldmatrix.sync.aligned.m8n8.x4.shared.b16 {%0,%1,%2,%3}, [%4];"
                 : "=r"(d0), "=r"(d1), "=r"(d2), "=r"(d3) : "r"(addr));
}

__device__ __forceinline__ uint32_t ex2h2(uint32_t h) {
    uint32_t r;
    asm("ex2.approx.f16x2 %0, %1;" : "=r"(r) : "r"(h));
    return r;
}

__device__ __forceinline__ void cpasync16(uint32_t dst, const void* src) {
    asm volatile("cp.async.cg.shared.global [%0], [%1], 16;" :: "r"(dst), "l"(src));
}
#define CP_COMMIT() asm volatile("cp.async.commit_group;" ::: "memory")

// ============================================================================
// Kernel A: fused QKV projection via mma.sync f16 (round-11 version verbatim).
// ============================================================================
#define WS_OFF  0
#define XS_OFF  6912
#define QST_OFF 9216
#define KST_OFF 11520
#define VST_OFF 13824
#define BS_OFF  16128
#define QKV_SMEM_BYTES ((16128 + 192) * 4)   // 65,280 B

__global__ __launch_bounds__(128, 3) void qkv_kernel(
    const float* __restrict__ x,
    const float* __restrict__ wq, const float* __restrict__ bq,
    const float* __restrict__ wk, const float* __restrict__ bk,
    const float* __restrict__ wv, const float* __restrict__ bv)
{
    extern __shared__ uint32_t smw[];
    uint32_t* ws  = smw + WS_OFF;               // [192][36] f16 pairs
    uint32_t* xs  = smw + XS_OFF;               // [64][36]
    __half*  qst  = (__half*)(smw + QST_OFF);   // [64][72]
    __half*  kst  = (__half*)(smw + KST_OFF);   // [64][72]
    __half*  vst  = (__half*)(smw + VST_OFF);   // [64 chan][72 pos]
    float*   bs   = (float*)(smw + BS_OFF);     // [192]
    const uint32_t sbase = smem_u32(smw);

    const int tid  = threadIdx.x;
    const int wid  = tid >> 5, lane = tid & 31;
    const int g    = lane >> 2, tig = lane & 3;
    const int b    = blockIdx.y;
    const int n0   = blockIdx.x * 64;
    const int p0   = wid * 16;

    for (int i = tid; i < 6144; i += 128) {
        int row = i >> 5, c2 = i & 31;
        const float* wsrc = (row < 64) ? wq : (row < 128) ? wk : wv;
        int r = row & 63;
        float w0 = wsrc[r * 64 + 2 * c2], w1 = wsrc[r * 64 + 2 * c2 + 1];
        if (row < 64) { w0 *= QSCALE; w1 *= QSCALE; }
        __half2 h = __floats2half2_rn(w0, w1);
        ws[row * 36 + c2] = *(uint32_t*)&h;
    }
    for (int i = tid; i < 192; i += 128) {
        bs[i] = (i < 64) ? bq[i] * QSCALE
              : (i < 128) ? bk[i - 64] : bv[i - 128];
    }
    for (int i = tid; i < 2048; i += 128) {
        int c2 = i >> 6, p = i & 63;
        float x0 = x[(b * 64 + 2 * c2    ) * NPOS + n0 + p];
        float x1 = x[(b * 64 + 2 * c2 + 1) * NPOS + n0 + p];
        __half2 h = __floats2half2_rn(x0, x1);
        xs[p * 36 + c2] = *(uint32_t*)&h;
    }
    __syncthreads();

    const int row_in = (lane & 7) | ((lane >> 4) << 3);
    const int woff   = ((lane >> 3) & 1) << 2;
    const uint32_t xLane = sbase + (uint32_t)((XS_OFF + (p0 + row_in) * 36 + woff) * 4);
    uint32_t bfr[4][4];
#pragma unroll
    for (int kk = 0; kk < 4; ++kk)
        ldsm4(bfr[kk][0], bfr[kk][1], bfr[kk][2], bfr[kk][3],
              xLane + (uint32_t)(kk * 32));

    const uint32_t aLaneBase = sbase
        + (uint32_t)(((lane & 15) * 36) * 4) + (uint32_t)(((lane >> 4) << 4));

    const int pA = p0 + 2 * tig;
    const int pB = pA + 8;

#pragma unroll
    for (int mb = 0; mb < 12; ++mb) {
        float d0[4] = {0.f, 0.f, 0.f, 0.f};
        float d1[4] = {0.f, 0.f, 0.f, 0.f};
        const uint32_t aL = aLaneBase + (uint32_t)(mb * 16 * 36 * 4);
#pragma unroll
        for (int kk = 0; kk < 4; ++kk) {
            uint32_t a[4];
            ldsm4(a[0], a[1], a[2], a[3], aL + (uint32_t)(kk * 32));
            mma_f16(d0, a, bfr[kk][0], bfr[kk][1], d0);
            mma_f16(d1, a, bfr[kk][2], bfr[kk][3], d1);
        }
        const int ch0 = mb * 16 + g, ch1 = ch0 + 8;
        const float bb0 = bs[ch0], bb1 = bs[ch1];
        if (mb < 8) {
            __half* st = (mb < 4) ? qst : kst;
            const int cc0 = ch0 & 63, cc1 = ch1 & 63;
            st[ pA      * 72 + cc0] = __float2half_rn(d0[0] + bb0);
            st[(pA + 1) * 72 + cc0] = __float2half_rn(d0[1] + bb0);
            st[ pA      * 72 + cc1] = __float2half_rn(d0[2] + bb1);
            st[(pA + 1) * 72 + cc1] = __float2half_rn(d0[3] + bb1);
            st[ pB      * 72 + cc0] = __float2half_rn(d1[0] + bb0);
            st[(pB + 1) * 72 + cc0] = __float2half_rn(d1[1] + bb0);
            st[ pB      * 72 + cc1] = __float2half_rn(d1[2] + bb1);
            st[(pB + 1) * 72 + cc1] = __float2half_rn(d1[3] + bb1);
        } else {
            const int cc0 = ch0 - 128, cc1 = ch1 - 128;
            *(__half2*)&vst[cc0 * 72 + pA] = __floats2half2_rn(d0[0] + bb0, d0[1] + bb0);
            *(__half2*)&vst[cc1 * 72 + pA] = __floats2half2_rn(d0[2] + bb1, d0[3] + bb1);
            *(__half2*)&vst[cc0 * 72 + pB] = __floats2half2_rn(d1[0] + bb0, d1[1] + bb0);
            *(__half2*)&vst[cc1 * 72 + pB] = __floats2half2_rn(d1[2] + bb1, d1[3] + bb1);
        }
    }
    __syncthreads();

    for (int i = tid; i < 512; i += 128) {
        int r = i >> 3, c8 = (i & 7) << 3;
        *(uint4*)&g_Qh[((b * NPOS) + n0 + r) * 64 + c8] =
            *(const uint4*)&qst[r * 72 + c8];
        *(uint4*)&g_Kh[((b * NPOS) + n0 + r) * 64 + c8] =
            *(const uint4*)&kst[r * 72 + c8];
    }
    for (int i = tid; i < 512; i += 128) {
        int r = i >> 3, p8 = (i & 7) << 3;
        *(uint4*)&g_Vt[((b * 64) + r) * NPOS + n0 + p8] =
            *(const uint4*)&vst[r * 72 + p8];
    }
}

// ============================================================================
// Kernel B: flash attention, warp-pool (round 13) + 256-key KV tiles.
//   32 kv iterations instead of 63 -> sync/pipeline overhead halves. Each
//   256-key tile is computed as two do_tile<8> calls (same register peak,
//   same proven layouts); tail tile (64 keys) is one do_tile<4>.
// ============================================================================
#define QSTW 36                   // Q/K row stride in words (72 f16)
#define VSTW 132                  // V row stride in words (264 f16: 256 + pad)
#define KTILE_B (256 * QSTW * 4)  // 36,864 B per K stage
#define VTILE_B (64 * VSTW * 4)   // 33,792 B per V stage
#define FLASH_SMEM_BYTES (128 * QSTW * 4 + 2 * KTILE_B + 2 * VTILE_B) // 159,744

template<int JMAX>
__device__ __forceinline__ void do_tile(uint32_t kb, uint32_t vb,
                                        const uint32_t qa[4][4],
                                        float ofrag[8][4],
                                        float& lsum0, float& lsum1)
{
    // ---- S phase ----
    uint32_t sfh[2 * JMAX][2];
#pragma unroll
    for (int nb = 0; nb < 2 * JMAX; ++nb) { sfh[nb][0] = 0u; sfh[nb][1] = 0u; }
#pragma unroll
    for (int k = 0; k < 4; ++k) {
#pragma unroll
        for (int j = 0; j < JMAX; ++j) {
            uint32_t d0, d1, d2, d3;
            ldsm4(d0, d1, d2, d3, kb + (uint32_t)((j * 16 * QSTW + 8 * k) * 4));
            mma_f16h(sfh[2 * j    ], qa[k], d0, d1, sfh[2 * j    ][0], sfh[2 * j    ][1]);
            mma_f16h(sfh[2 * j + 1], qa[k], d2, d3, sfh[2 * j + 1][0], sfh[2 * j + 1][1]);
        }
    }

    // ---- exp phase ----
    uint32_t pa[JMAX][4];
#pragma unroll
    for (int j = 0; j < JMAX; ++j) {
        pa[j][0] = ex2h2(sfh[2 * j    ][0]);
        pa[j][1] = ex2h2(sfh[2 * j    ][1]);
        pa[j][2] = ex2h2(sfh[2 * j + 1][0]);
        pa[j][3] = ex2h2(sfh[2 * j + 1][1]);
    }

    // ---- row sums via HADD2 on the FMA pipe ----
    {
        __half2 h0 = __floats2half2_rn(0.f, 0.f);
        __half2 h1 = h0;
#pragma unroll
        for (int j = 0; j < JMAX; ++j) {
            h0 = __hadd2(h0, *(const __half2*)&pa[j][0]);
            h0 = __hadd2(h0, *(const __half2*)&pa[j][2]);
            h1 = __hadd2(h1, *(const __half2*)&pa[j][1]);
            h1 = __hadd2(h1, *(const __half2*)&pa[j][3]);
        }
        lsum0 += __low2float(h0) + __high2float(h0);
        lsum1 += __low2float(h1) + __high2float(h1);
    }

    // ---- PV phase ----
#pragma unroll
    for (int j = 0; j < JMAX; ++j) {
#pragma unroll
        for (int nb2 = 0; nb2 < 4; ++nb2) {
            uint32_t v0, v1, v2, v3;
            ldsm4(v0, v1, v2, v3, vb + (uint32_t)((nb2 * 16 * VSTW + 8 * j) * 4));
            mma_f16(ofrag[2 * nb2    ], pa[j], v0, v1, ofrag[2 * nb2    ]);
            mma_f16(ofrag[2 * nb2 + 1], pa[j], v2, v3, ofrag[2 * nb2 + 1]);
        }
    }
}

__global__ __launch_bounds__(256, 1) void flash_mma_kernel()
{
    extern __shared__ uint32_t smw[];
    uint32_t* Qw = smw;                              // [128][36]
    const uint32_t sbase  = smem_u32(smw);
    const uint32_t kbase0 = sbase + 128 * QSTW * 4;
    const uint32_t vbase0 = kbase0 + 2 * KTILE_B;

    const int tid  = threadIdx.x;
    const int wid  = tid >> 5, lane = tid & 31;
    const int g    = lane >> 2, tig = lane & 3;
    const int b    = blockIdx.x / NCPB;              // batch
    const int c    = blockIdx.x % NCPB;              // CTA index within batch
    const int item = c + NCPB * wid;                 // this warp's row-item
    const bool valid = (item < NITEMS);
    const int rbase = item * 16;                     // global q-row base
    const int rb   = wid * 16;                       // smem Q row base

    // ---- Q fill: each ACTIVE warp stages its own 16 rows ----
    if (valid) {
#pragma unroll
        for (int i = 0; i < 4; ++i) {
            int idx = lane + 32 * i;                 // 128 uint4 per warp
            int rr = idx >> 3, c8 = (idx & 7) << 3;
            uint4 v = *(const uint4*)&g_Qh[((b * NPOS) + rbase + rr) * 64 + c8];
            *(uint4*)&Qw[(rb + rr) * QSTW + (c8 >> 1)] = v;
        }
    }
    __syncthreads();

    uint32_t qa[4][4];
#pragma unroll
    for (int k = 0; k < 4; ++k) {
        qa[k][0] = Qw[(rb + g    ) * QSTW + 8 * k + tig];
        qa[k][1] = Qw[(rb + g + 8) * QSTW + 8 * k + tig];
        qa[k][2] = Qw[(rb + g    ) * QSTW + 8 * k + tig + 4];
        qa[k][3] = Qw[(rb + g + 8) * QSTW + 8 * k + tig + 4];
    }

    const int row_in = (lane & 7) | ((lane >> 4) << 3);
    const int woff   = ((lane >> 3) & 1) << 2;
    const uint32_t kLane = (uint32_t)((row_in * QSTW + woff) * 4);
    const uint32_t vLane = (uint32_t)((row_in * VSTW + woff) * 4);

    float ofrag[8][4];
#pragma unroll
    for (int nb = 0; nb < 8; ++nb)
#pragma unroll
        for (int i = 0; i < 4; ++i) ofrag[nb][i] = 0.f;
    float lsum0 = 0.f, lsum1 = 0.f;

    // fill one 256-key stage (K: 256 rows x 128 B, V: 64 chans x 512 B)
    auto fill_async = [&](int t, uint32_t kdst, uint32_t vdst) {
        const int kv0 = t * 256;
#pragma unroll
        for (int i = 0; i < 8; ++i) {                // K: 2048 uint4
            int idx = tid + i * 256;
            int r = idx >> 3, c8 = (idx & 7) << 3;
            cpasync16(kdst + (uint32_t)((r * QSTW + (c8 >> 1)) * 4),
                      &g_Kh[((size_t)(b * NPOS) + kv0 + r) * 64 + c8]);
        }
#pragma unroll
        for (int i = 0; i < 8; ++i) {                // V: 2048 uint4
            int idx = tid + i * 256;
            int cc = idx >> 5, k8 = (idx & 31) << 3;
            cpasync16(vdst + (uint32_t)((cc * VSTW + (k8 >> 1)) * 4),
                      &g_Vt[((size_t)(b * 64) + cc) * NPOS + kv0 + k8]);
        }
    };

    fill_async(0, kbase0, vbase0);
    CP_COMMIT();

#pragma unroll 1
    for (int t = 0; t < NKT; ++t) {
        __syncthreads();
        const int cur = t & 1;
        if (t + 1 < NKT) {
            fill_async(t + 1, kbase0 + (uint32_t)(((t + 1) & 1) * KTILE_B),
                              vbase0 + (uint32_t)(((t + 1) & 1) * VTILE_B));
            CP_COMMIT();
            asm volatile("cp.async.wait_group 1;" ::: "memory");
        } else {
            asm volatile("cp.async.wait_group 0;" ::: "memory");
        }
        __syncthreads();

        if (!valid) continue;           // idle warps still did fills + syncs

        const uint32_t kb = kbase0 + (uint32_t)(cur * KTILE_B) + kLane;
        const uint32_t vb = vbase0 + (uint32_t)(cur * VTILE_B) + vLane;

        if (t < NKT - 1) {
            // full 256-key tile: two 128-key halves with the proven body
            do_tile<8>(kb, vb, qa, ofrag, lsum0, lsum1);
            do_tile<8>(kb + (uint32_t)(128 * QSTW * 4), vb + 256u,
                       qa, ofrag, lsum0, lsum1);
        } else {
            // tail: keys 7936..7999 (64 keys)
            do_tile<4>(kb, vb, qa, ofrag, lsum0, lsum1);
        }
    }

    if (!valid) return;

    // ---- epilogue: reduce row sums over the 4 tig lanes, normalize, store ----
    lsum0 += __shfl_xor_sync(0xffffffffu, lsum0, 1);
    lsum0 += __shfl_xor_sync(0xffffffffu, lsum0, 2);
    lsum1 += __shfl_xor_sync(0xffffffffu, lsum1, 1);
    lsum1 += __shfl_xor_sync(0xffffffffu, lsum1, 2);
    const float inv0 = 1.0f / lsum0;
    const float inv1 = 1.0f / lsum1;

    const int r0 = rbase + g, r1 = rbase + g + 8;
#pragma unroll
    for (int nb = 0; nb < 8; ++nb) {
        *(float2*)&g_O[((b * NPOS) + r0) * 64 + nb * 8 + 2 * tig]
            = make_float2(ofrag[nb][0] * inv0, ofrag[nb][1] * inv0);
        *(float2*)&g_O[((b * NPOS) + r1) * 64 + nb * 8 + 2 * tig]
            = make_float2(ofrag[nb][2] * inv1, ofrag[nb][3] * inv1);
    }
}

// ============================================================================
// Kernel C: output projection, 512 threads (round-11 version verbatim).
// ============================================================================
__global__ __launch_bounds__(512) void out_proj_kernel(
    float* __restrict__ out,
    const float* __restrict__ wo, const float* __restrict__ bo)
{
    __shared__ float wos[4096];
    __shared__ float os[64 * 68];

    const int tid = threadIdx.x;
    const int b   = blockIdx.y;
    const int bx  = blockIdx.x;

    for (int i = tid; i < 4096; i += 512) wos[i] = wo[i];
    for (int i = tid; i < 4096; i += 512) {
        int c = i >> 6, pl = i & 63;
        os[pl * 68 + c] = g_O[((b * NPOS) + c * 125 + bx) * 64 + pl];
    }
    __syncthreads();

    const int pl = tid & 63;
    const int o0 = (tid >> 6) << 3;

    float acc[8];
#pragma unroll
    for (int j = 0; j < 8; ++j) acc[j] = 0.f;

#pragma unroll 8
    for (int c = 0; c < 64; c += 4) {
        float4 xv = *(const float4*)&os[pl * 68 + c];
#pragma unroll
        for (int j = 0; j < 8; ++j) {
            float4 w4 = *(const float4*)&wos[(o0 + j) * 64 + c];
            acc[j] += w4.x * xv.x + w4.y * xv.y + w4.z * xv.z + w4.w * xv.w;
        }
    }
#pragma unroll
    for (int j = 0; j < 8; ++j)
        out[((b * 64) + o0 + j) * NPOS + bx * 64 + pl] = acc[j] + bo[o0 + j];
}

// ============================================================================
extern "C" void kernel_launch(void* const* d_in, const int* in_sizes, int n_in,
                              void* d_out, int out_size)
{
    (void)in_sizes; (void)n_in; (void)out_size;
    const float* x  = (const float*)d_in[0];
    const float* wq = (const float*)d_in[1];
    const float* bq = (const float*)d_in[2];
    const float* wk = (const float*)d_in[3];
    const float* bk = (const float*)d_in[4];
    const float* wv = (const float*)d_in[5];
    const float* bv = (const float*)d_in[6];
    const float* wo = (const float*)d_in[7];
    const float* bo = (const float*)d_in[8];
    float* out = (float*)d_out;

    cudaFuncSetAttribute(qkv_kernel,
                         cudaFuncAttributeMaxDynamicSharedMemorySize, QKV_SMEM_BYTES);
    cudaFuncSetAttribute(flash_mma_kernel,
                         cudaFuncAttributeMaxDynamicSharedMemorySize, FLASH_SMEM_BYTES);

    qkv_kernel<<<dim3(125, BATCH), 128, QKV_SMEM_BYTES>>>(x, wq, bq, wk, bk, wv, bv);
    flash_mma_kernel<<<BATCH * NCPB, 256, FLASH_SMEM_BYTES>>>();
    out_proj_kernel<<<dim3(125, BATCH), 512>>>(out, wo, bo);
}

// round 15
// speedup vs baseline: 1.1265x; 1.0160x over previous
#include <cuda_runtime.h>
#include <cuda_fp16.h>
#include <cstdint>

// ---------------- problem constants ----------------
#define BATCH 2
#define NPOS  8000          // 20*20*20
#define NKT   32            // kv tiles of 256 keys: 31 full + 1 tail (64 keys)
#define NITEMS 500          // warp-items per batch (8000 rows / 16)
#define NCPB   72           // CTAs per batch in flash

// -------- device scratch (padded: tail fills read K rows/V keys to 8191) ----
__device__ __half g_Qh[BATCH * NPOS * 64];           // (b, n, k) pre-scaled
__device__ __half g_Kh[BATCH * NPOS * 64 + 16384];   // (b, n, k)
__device__ __half g_Vt[BATCH * 64 * NPOS + 16384];   // (b, c, n) transposed
__device__ float  g_O [BATCH * NPOS * 64];           // (b, n, c) fp32
__device__ uint32_t g_W16[192 * 36];                 // f16 W image (smem layout)
__device__ float    g_B[192];                        // scaled biases

#define QSCALE (0.125f * 1.44269504f)   // 1/sqrt(64) * log2(e), folded into Wq

// ---------------- PTX helpers ----------------
__device__ __forceinline__ uint32_t smem_u32(const void* p) {
    uint32_t a;
    asm("{ .reg .u64 t; cvta.to.shared.u64 t, %1; cvt.u32.u64 %0, t; }"
        : "=r"(a) : "l"(p));
    return a;
}

__device__ __forceinline__ void mma_f16(float d[4], const uint32_t a[4],
                                        const uint32_t b0, const uint32_t b1,
                                        const float c[4]) {
    asm volatile(
        "mma.sync.aligned.m16n8k16.row.col.f32.f16.f16.f32 "
        "{%0,%1,%2,%3}, {%4,%5,%6,%7}, {%8,%9}, {%10,%11,%12,%13};"
        : "=f"(d[0]), "=f"(d[1]), "=f"(d[2]), "=f"(d[3])
        : "r"(a[0]), "r"(a[1]), "r"(a[2]), "r"(a[3]),
          "r"(b0), "r"(b1),
          "f"(c[0]), "f"(c[1]), "f"(c[2]), "f"(c[3]));
}

__device__ __forceinline__ void mma_f16h(uint32_t d[2], const uint32_t a[4],
                                         const uint32_t b0, const uint32_t b1,
                                         const uint32_t c0, const uint32_t c1) {
    asm volatile(
        "mma.sync.aligned.m16n8k16.row.col.f16.f16.f16.f16 "
        "{%0,%1}, {%2,%3,%4,%5}, {%6,%7}, {%8,%9};"
        : "=r"(d[0]), "=r"(d[1])
        : "r"(a[0]), "r"(a[1]), "r"(a[2]), "r"(a[3]),
          "r"(b0), "r"(b1), "r"(c0), "r"(c1));
}

__device__ __forceinline__ void ldsm4(uint32_t& d0, uint32_t& d1,
                                      uint32_t& d2, uint32_t& d3, uint32_t addr) {
    asm volatile("ldmatrix.sync.aligned.m8n8.x4.shared.b16 {%0,%1,%2,%3}, [%4];"
                 : "=r"(d0), "=r"(d1), "=r"(d2), "=r"(d3) : "r"(addr));
}

__device__ __forceinline__ uint32_t ex2h2(uint32_t h) {
    uint32_t r;
    asm("ex2.approx.f16x2 %0, %1;" : "=r"(r) : "r"(h));
    return r;
}

__device__ __forceinline__ void cpasync16(uint32_t dst, const void* src) {
    asm volatile("cp.async.cg.shared.global [%0], [%1], 16;" :: "r"(dst), "l"(src));
}
#define CP_COMMIT() asm volatile("cp.async.commit_group;" ::: "memory")

// ============================================================================
// Kernel 0: weight prep — convert W (q|k|v stacked, scales folded) to the
// padded f16 smem image once, instead of per-CTA in qkv.
// ============================================================================
__global__ __launch_bounds__(512) void prep_kernel(
    const float* __restrict__ wq, const float* __restrict__ bq,
    const float* __restrict__ wk, const float* __restrict__ bk,
    const float* __restrict__ wv, const float* __restrict__ bv)
{
    const int i = blockIdx.x * 512 + threadIdx.x;
    if (i < 6144) {
        int row = i >> 5, c2 = i & 31;
        const float* wsrc = (row < 64) ? wq : (row < 128) ? wk : wv;
        int r = row & 63;
        float w0 = wsrc[r * 64 + 2 * c2], w1 = wsrc[r * 64 + 2 * c2 + 1];
        if (row < 64) { w0 *= QSCALE; w1 *= QSCALE; }
        __half2 h = __floats2half2_rn(w0, w1);
        g_W16[row * 36 + c2] = *(uint32_t*)&h;
    }
    if (i < 192) {
        g_B[i] = (i < 64) ? bq[i] * QSCALE
               : (i < 128) ? bk[i - 64] : bv[i - 128];
    }
}

// ============================================================================
// Kernel A: fused QKV projection via mma.sync f16.
//   W image + bias arrive via cp.async (overlapped with the x-transpose fill);
//   no per-CTA conversion work. CTA = 64 positions, 128 threads, grid (125,2).
// ============================================================================
#define WS_OFF  0
#define XS_OFF  6912
#define QST_OFF 9216
#define KST_OFF 11520
#define VST_OFF 13824
#define BS_OFF  16128
#define QKV_SMEM_BYTES ((16128 + 192) * 4)   // 65,280 B

__global__ __launch_bounds__(128, 3) void qkv_kernel(const float* __restrict__ x)
{
    extern __shared__ uint32_t smw[];
    uint32_t* xs  = smw + XS_OFF;               // [64][36]
    __half*  qst  = (__half*)(smw + QST_OFF);   // [64][72]
    __half*  kst  = (__half*)(smw + KST_OFF);   // [64][72]
    __half*  vst  = (__half*)(smw + VST_OFF);   // [64 chan][72 pos]
    float*   bs   = (float*)(smw + BS_OFF);     // [192]
    const uint32_t sbase = smem_u32(smw);

    const int tid  = threadIdx.x;
    const int wid  = tid >> 5, lane = tid & 31;
    const int g    = lane >> 2, tig = lane & 3;
    const int b    = blockIdx.y;
    const int n0   = blockIdx.x * 64;
    const int p0   = wid * 16;

    // ---- W image + bias via cp.async (1728 + 48 uint4) ----
    for (int i = tid; i < 1728; i += 128)
        cpasync16(sbase + (uint32_t)(i * 16), (const uint4*)g_W16 + i);
    if (tid < 48)
        cpasync16(sbase + (uint32_t)(BS_OFF * 4 + tid * 16), (const uint4*)g_B + tid);
    CP_COMMIT();

    // ---- x fill (overlaps the async W copy) ----
    for (int i = tid; i < 2048; i += 128) {
        int c2 = i >> 6, p = i & 63;
        float x0 = x[(b * 64 + 2 * c2    ) * NPOS + n0 + p];
        float x1 = x[(b * 64 + 2 * c2 + 1) * NPOS + n0 + p];
        __half2 h = __floats2half2_rn(x0, x1);
        xs[p * 36 + c2] = *(uint32_t*)&h;
    }
    asm volatile("cp.async.wait_group 0;" ::: "memory");
    __syncthreads();

    // ---- B-fragments: this warp's 16 positions, all 64 k ----
    const int row_in = (lane & 7) | ((lane >> 4) << 3);
    const int woff   = ((lane >> 3) & 1) << 2;
    const uint32_t xLane = sbase + (uint32_t)((XS_OFF + (p0 + row_in) * 36 + woff) * 4);
    uint32_t bfr[4][4];
#pragma unroll
    for (int kk = 0; kk < 4; ++kk)
        ldsm4(bfr[kk][0], bfr[kk][1], bfr[kk][2], bfr[kk][3],
              xLane + (uint32_t)(kk * 32));

    const uint32_t aLaneBase = sbase
        + (uint32_t)(((lane & 15) * 36) * 4) + (uint32_t)(((lane >> 4) << 4));

    const int pA = p0 + 2 * tig;
    const int pB = pA + 8;

#pragma unroll
    for (int mb = 0; mb < 12; ++mb) {
        float d0[4] = {0.f, 0.f, 0.f, 0.f};
        float d1[4] = {0.f, 0.f, 0.f, 0.f};
        const uint32_t aL = aLaneBase + (uint32_t)(mb * 16 * 36 * 4);
#pragma unroll
        for (int kk = 0; kk < 4; ++kk) {
            uint32_t a[4];
            ldsm4(a[0], a[1], a[2], a[3], aL + (uint32_t)(kk * 32));
            mma_f16(d0, a, bfr[kk][0], bfr[kk][1], d0);
            mma_f16(d1, a, bfr[kk][2], bfr[kk][3], d1);
        }
        const int ch0 = mb * 16 + g, ch1 = ch0 + 8;
        const float bb0 = bs[ch0], bb1 = bs[ch1];
        if (mb < 8) {
            __half* st = (mb < 4) ? qst : kst;
            const int cc0 = ch0 & 63, cc1 = ch1 & 63;
            st[ pA      * 72 + cc0] = __float2half_rn(d0[0] + bb0);
            st[(pA + 1) * 72 + cc0] = __float2half_rn(d0[1] + bb0);
            st[ pA      * 72 + cc1] = __float2half_rn(d0[2] + bb1);
            st[(pA + 1) * 72 + cc1] = __float2half_rn(d0[3] + bb1);
            st[ pB      * 72 + cc0] = __float2half_rn(d1[0] + bb0);
            st[(pB + 1) * 72 + cc0] = __float2half_rn(d1[1] + bb0);
            st[ pB      * 72 + cc1] = __float2half_rn(d1[2] + bb1);
            st[(pB + 1) * 72 + cc1] = __float2half_rn(d1[3] + bb1);
        } else {
            const int cc0 = ch0 - 128, cc1 = ch1 - 128;
            *(__half2*)&vst[cc0 * 72 + pA] = __floats2half2_rn(d0[0] + bb0, d0[1] + bb0);
            *(__half2*)&vst[cc1 * 72 + pA] = __floats2half2_rn(d0[2] + bb1, d0[3] + bb1);
            *(__half2*)&vst[cc0 * 72 + pB] = __floats2half2_rn(d1[0] + bb0, d1[1] + bb0);
            *(__half2*)&vst[cc1 * 72 + pB] = __floats2half2_rn(d1[2] + bb1, d1[3] + bb1);
        }
    }
    __syncthreads();

    for (int i = tid; i < 512; i += 128) {
        int r = i >> 3, c8 = (i & 7) << 3;
        *(uint4*)&g_Qh[((b * NPOS) + n0 + r) * 64 + c8] =
            *(const uint4*)&qst[r * 72 + c8];
        *(uint4*)&g_Kh[((b * NPOS) + n0 + r) * 64 + c8] =
            *(const uint4*)&kst[r * 72 + c8];
    }
    for (int i = tid; i < 512; i += 128) {
        int r = i >> 3, p8 = (i & 7) << 3;
        *(uint4*)&g_Vt[((b * 64) + r) * NPOS + n0 + p8] =
            *(const uint4*)&vst[r * 72 + p8];
    }
}

// ============================================================================
// Kernel B: flash attention (round-14 version verbatim: warp-pool + 256-key
// KV tiles; HMMA-rate-bound floor for this harness).
// ============================================================================
#define QSTW 36                   // Q/K row stride in words (72 f16)
#define VSTW 132                  // V row stride in words (264 f16: 256 + pad)
#define KTILE_B (256 * QSTW * 4)  // 36,864 B per K stage
#define VTILE_B (64 * VSTW * 4)   // 33,792 B per V stage
#define FLASH_SMEM_BYTES (128 * QSTW * 4 + 2 * KTILE_B + 2 * VTILE_B) // 159,744

template<int JMAX>
__device__ __forceinline__ void do_tile(uint32_t kb, uint32_t vb,
                                        const uint32_t qa[4][4],
                                        float ofrag[8][4],
                                        float& lsum0, float& lsum1)
{
    uint32_t sfh[2 * JMAX][2];
#pragma unroll
    for (int nb = 0; nb < 2 * JMAX; ++nb) { sfh[nb][0] = 0u; sfh[nb][1] = 0u; }
#pragma unroll
    for (int k = 0; k < 4; ++k) {
#pragma unroll
        for (int j = 0; j < JMAX; ++j) {
            uint32_t d0, d1, d2, d3;
            ldsm4(d0, d1, d2, d3, kb + (uint32_t)((j * 16 * QSTW + 8 * k) * 4));
            mma_f16h(sfh[2 * j    ], qa[k], d0, d1, sfh[2 * j    ][0], sfh[2 * j    ][1]);
            mma_f16h(sfh[2 * j + 1], qa[k], d2, d3, sfh[2 * j + 1][0], sfh[2 * j + 1][1]);
        }
    }

    uint32_t pa[JMAX][4];
#pragma unroll
    for (int j = 0; j < JMAX; ++j) {
        pa[j][0] = ex2h2(sfh[2 * j    ][0]);
        pa[j][1] = ex2h2(sfh[2 * j    ][1]);
        pa[j][2] = ex2h2(sfh[2 * j + 1][0]);
        pa[j][3] = ex2h2(sfh[2 * j + 1][1]);
    }

    {
        __half2 h0 = __floats2half2_rn(0.f, 0.f);
        __half2 h1 = h0;
#pragma unroll
        for (int j = 0; j < JMAX; ++j) {
            h0 = __hadd2(h0, *(const __half2*)&pa[j][0]);
            h0 = __hadd2(h0, *(const __half2*)&pa[j][2]);
            h1 = __hadd2(h1, *(const __half2*)&pa[j][1]);
            h1 = __hadd2(h1, *(const __half2*)&pa[j][3]);
        }
        lsum0 += __low2float(h0) + __high2float(h0);
        lsum1 += __low2float(h1) + __high2float(h1);
    }

#pragma unroll
    for (int j = 0; j < JMAX; ++j) {
#pragma unroll
        for (int nb2 = 0; nb2 < 4; ++nb2) {
            uint32_t v0, v1, v2, v3;
            ldsm4(v0, v1, v2, v3, vb + (uint32_t)((nb2 * 16 * VSTW + 8 * j) * 4));
            mma_f16(ofrag[2 * nb2    ], pa[j], v0, v1, ofrag[2 * nb2    ]);
            mma_f16(ofrag[2 * nb2 + 1], pa[j], v2, v3, ofrag[2 * nb2 + 1]);
        }
    }
}

__global__ __launch_bounds__(256, 1) void flash_mma_kernel()
{
    extern __shared__ uint32_t smw[];
    uint32_t* Qw = smw;                              // [128][36]
    const uint32_t sbase  = smem_u32(smw);
    const uint32_t kbase0 = sbase + 128 * QSTW * 4;
    const uint32_t vbase0 = kbase0 + 2 * KTILE_B;

    const int tid  = threadIdx.x;
    const int wid  = tid >> 5, lane = tid & 31;
    const int g    = lane >> 2, tig = lane & 3;
    const int b    = blockIdx.x / NCPB;
    const int c    = blockIdx.x % NCPB;
    const int item = c + NCPB * wid;
    const bool valid = (item < NITEMS);
    const int rbase = item * 16;
    const int rb   = wid * 16;

    if (valid) {
#pragma unroll
        for (int i = 0; i < 4; ++i) {
            int idx = lane + 32 * i;
            int rr = idx >> 3, c8 = (idx & 7) << 3;
            uint4 v = *(const uint4*)&g_Qh[((b * NPOS) + rbase + rr) * 64 + c8];
            *(uint4*)&Qw[(rb + rr) * QSTW + (c8 >> 1)] = v;
        }
    }
    __syncthreads();

    uint32_t qa[4][4];
#pragma unroll
    for (int k = 0; k < 4; ++k) {
        qa[k][0] = Qw[(rb + g    ) * QSTW + 8 * k + tig];
        qa[k][1] = Qw[(rb + g + 8) * QSTW + 8 * k + tig];
        qa[k][2] = Qw[(rb + g    ) * QSTW + 8 * k + tig + 4];
        qa[k][3] = Qw[(rb + g + 8) * QSTW + 8 * k + tig + 4];
    }

    const int row_in = (lane & 7) | ((lane >> 4) << 3);
    const int woff   = ((lane >> 3) & 1) << 2;
    const uint32_t kLane = (uint32_t)((row_in * QSTW + woff) * 4);
    const uint32_t vLane = (uint32_t)((row_in * VSTW + woff) * 4);

    float ofrag[8][4];
#pragma unroll
    for (int nb = 0; nb < 8; ++nb)
#pragma unroll
        for (int i = 0; i < 4; ++i) ofrag[nb][i] = 0.f;
    float lsum0 = 0.f, lsum1 = 0.f;

    auto fill_async = [&](int t, uint32_t kdst, uint32_t vdst) {
        const int kv0 = t * 256;
#pragma unroll
        for (int i = 0; i < 8; ++i) {
            int idx = tid + i * 256;
            int r = idx >> 3, c8 = (idx & 7) << 3;
            cpasync16(kdst + (uint32_t)((r * QSTW + (c8 >> 1)) * 4),
                      &g_Kh[((size_t)(b * NPOS) + kv0 + r) * 64 + c8]);
        }
#pragma unroll
        for (int i = 0; i < 8; ++i) {
            int idx = tid + i * 256;
            int cc = idx >> 5, k8 = (idx & 31) << 3;
            cpasync16(vdst + (uint32_t)((cc * VSTW + (k8 >> 1)) * 4),
                      &g_Vt[((size_t)(b * 64) + cc) * NPOS + kv0 + k8]);
        }
    };

    fill_async(0, kbase0, vbase0);
    CP_COMMIT();

#pragma unroll 1
    for (int t = 0; t < NKT; ++t) {
        __syncthreads();
        const int cur = t & 1;
        if (t + 1 < NKT) {
            fill_async(t + 1, kbase0 + (uint32_t)(((t + 1) & 1) * KTILE_B),
                              vbase0 + (uint32_t)(((t + 1) & 1) * VTILE_B));
            CP_COMMIT();
            asm volatile("cp.async.wait_group 1;" ::: "memory");
        } else {
            asm volatile("cp.async.wait_group 0;" ::: "memory");
        }
        __syncthreads();

        if (!valid) continue;

        const uint32_t kb = kbase0 + (uint32_t)(cur * KTILE_B) + kLane;
        const uint32_t vb = vbase0 + (uint32_t)(cur * VTILE_B) + vLane;

        if (t < NKT - 1) {
            do_tile<8>(kb, vb, qa, ofrag, lsum0, lsum1);
            do_tile<8>(kb + (uint32_t)(128 * QSTW * 4), vb + 256u,
                       qa, ofrag, lsum0, lsum1);
        } else {
            do_tile<4>(kb, vb, qa, ofrag, lsum0, lsum1);
        }
    }

    if (!valid) return;

    lsum0 += __shfl_xor_sync(0xffffffffu, lsum0, 1);
    lsum0 += __shfl_xor_sync(0xffffffffu, lsum0, 2);
    lsum1 += __shfl_xor_sync(0xffffffffu, lsum1, 1);
    lsum1 += __shfl_xor_sync(0xffffffffu, lsum1, 2);
    const float inv0 = 1.0f / lsum0;
    const float inv1 = 1.0f / lsum1;

    const int r0 = rbase + g, r1 = rbase + g + 8;
#pragma unroll
    for (int nb = 0; nb < 8; ++nb) {
        *(float2*)&g_O[((b * NPOS) + r0) * 64 + nb * 8 + 2 * tig]
            = make_float2(ofrag[nb][0] * inv0, ofrag[nb][1] * inv0);
        *(float2*)&g_O[((b * NPOS) + r1) * 64 + nb * 8 + 2 * tig]
            = make_float2(ofrag[nb][2] * inv1, ofrag[nb][3] * inv1);
    }
}

// ============================================================================
// Kernel C: output projection, 512 threads, 2 position-tiles per CTA
// (wos load amortized 2x). grid (63, 2); bx = blockIdx.x and blockIdx.x + 63.
//   y[b,o,p] = bo[o] + sum_c wo[o,c] * O[b, c*125 + (p>>6), p&63]
// ============================================================================
__global__ __launch_bounds__(512) void out_proj_kernel(
    float* __restrict__ out,
    const float* __restrict__ wo, const float* __restrict__ bo)
{
    __shared__ float wos[4096];
    __shared__ float os[64 * 68];

    const int tid = threadIdx.x;
    const int b   = blockIdx.y;

    for (int i = tid; i < 4096; i += 512) wos[i] = wo[i];

    const int pl = tid & 63;
    const int o0 = (tid >> 6) << 3;

#pragma unroll 1
    for (int s = 0; s < 2; ++s) {
        const int bx = blockIdx.x + 63 * s;     // 0..62, then 63..125
        if (bx >= 125) break;

        __syncthreads();                        // os reuse + (s=0) wos ready
        for (int i = tid; i < 4096; i += 512) {
            int c = i >> 6, p = i & 63;
            os[p * 68 + c] = g_O[((b * NPOS) + c * 125 + bx) * 64 + p];
        }
        __syncthreads();

        float acc[8];
#pragma unroll
        for (int j = 0; j < 8; ++j) acc[j] = 0.f;

#pragma unroll 8
        for (int c = 0; c < 64; c += 4) {
            float4 xv = *(const float4*)&os[pl * 68 + c];
#pragma unroll
            for (int j = 0; j < 8; ++j) {
                float4 w4 = *(const float4*)&wos[(o0 + j) * 64 + c];
                acc[j] += w4.x * xv.x + w4.y * xv.y + w4.z * xv.z + w4.w * xv.w;
            }
        }
#pragma unroll
        for (int j = 0; j < 8; ++j)
            out[((b * 64) + o0 + j) * NPOS + bx * 64 + pl] = acc[j] + bo[o0 + j];
    }
}

// ============================================================================
extern "C" void kernel_launch(void* const* d_in, const int* in_sizes, int n_in,
                              void* d_out, int out_size)
{
    (void)in_sizes; (void)n_in; (void)out_size;
    const float* x  = (const float*)d_in[0];
    const float* wq = (const float*)d_in[1];
    const float* bq = (const float*)d_in[2];
    const float* wk = (const float*)d_in[3];
    const float* bk = (const float*)d_in[4];
    const float* wv = (const float*)d_in[5];
    const float* bv = (const float*)d_in[6];
    const float* wo = (const float*)d_in[7];
    const float* bo = (const float*)d_in[8];
    float* out = (float*)d_out;

    cudaFuncSetAttribute(qkv_kernel,
                         cudaFuncAttributeMaxDynamicSharedMemorySize, QKV_SMEM_BYTES);
    cudaFuncSetAttribute(flash_mma_kernel,
                         cudaFuncAttributeMaxDynamicSharedMemorySize, FLASH_SMEM_BYTES);

    prep_kernel<<<12, 512>>>(wq, bq, wk, bk, wv, bv);
    qkv_kernel<<<dim3(125, BATCH), 128, QKV_SMEM_BYTES>>>(x);
    flash_mma_kernel<<<BATCH * NCPB, 256, FLASH_SMEM_BYTES>>>();
    out_proj_kernel<<<dim3(63, BATCH), 512>>>(out, wo, bo);
}

// round 16
// speedup vs baseline: 1.1696x; 1.0382x over previous
#include <cuda_runtime.h>
#include <cuda_fp16.h>
#include <cstdint>

// ---------------- problem constants ----------------
#define BATCH 2
#define NPOS  8000          // 20*20*20
#define NKT   32            // kv tiles of 256 keys: 31 full + 1 tail (64 keys)
#define NITEMS 500          // warp-items per batch (8000 rows / 16)
#define NCPB   72           // CTAs per batch in flash

// -------- device scratch (padded: tail fills read K rows/V keys to 8191) ----
__device__ __half g_Qh[BATCH * NPOS * 64];           // (b, n, k) pre-scaled
__device__ __half g_Kh[BATCH * NPOS * 64 + 16384];   // (b, n, k)
__device__ __half g_Vt[BATCH * 64 * NPOS + 16384];   // (b, c, n) transposed
__device__ float  g_O [BATCH * NPOS * 64];           // (b, n, c) fp32
__device__ uint32_t g_W16[192 * 36];                 // f16 qkv W image
__device__ float    g_B[192];                        // scaled qkv biases
__device__ uint32_t g_WO16[64 * 36];                 // f16 wo image
__device__ float    g_BO[64];                        // bo

#define QSCALE (0.125f * 1.44269504f)   // 1/sqrt(64) * log2(e), folded into Wq

// ---------------- PTX helpers ----------------
__device__ __forceinline__ uint32_t smem_u32(const void* p) {
    uint32_t a;
    asm("{ .reg .u64 t; cvta.to.shared.u64 t, %1; cvt.u32.u64 %0, t; }"
        : "=r"(a) : "l"(p));
    return a;
}

__device__ __forceinline__ void mma_f16(float d[4], const uint32_t a[4],
                                        const uint32_t b0, const uint32_t b1,
                                        const float c[4]) {
    asm volatile(
        "mma.sync.aligned.m16n8k16.row.col.f32.f16.f16.f32 "
        "{%0,%1,%2,%3}, {%4,%5,%6,%7}, {%8,%9}, {%10,%11,%12,%13};"
        : "=f"(d[0]), "=f"(d[1]), "=f"(d[2]), "=f"(d[3])
        : "r"(a[0]), "r"(a[1]), "r"(a[2]), "r"(a[3]),
          "r"(b0), "r"(b1),
          "f"(c[0]), "f"(c[1]), "f"(c[2]), "f"(c[3]));
}

__device__ __forceinline__ void mma_f16h(uint32_t d[2], const uint32_t a[4],
                                         const uint32_t b0, const uint32_t b1,
                                         const uint32_t c0, const uint32_t c1) {
    asm volatile(
        "mma.sync.aligned.m16n8k16.row.col.f16.f16.f16.f16 "
        "{%0,%1}, {%2,%3,%4,%5}, {%6,%7}, {%8,%9};"
        : "=r"(d[0]), "=r"(d[1])
        : "r"(a[0]), "r"(a[1]), "r"(a[2]), "r"(a[3]),
          "r"(b0), "r"(b1), "r"(c0), "r"(c1));
}

__device__ __forceinline__ void ldsm4(uint32_t& d0, uint32_t& d1,
                                      uint32_t& d2, uint32_t& d3, uint32_t addr) {
    asm volatile("ldmatrix.sync.aligned.m8n8.x4.shared.b16 {%0,%1,%2,%3}, [%4];"
                 : "=r"(d0), "=r"(d1), "=r"(d2), "=r"(d3) : "r"(addr));
}

__device__ __forceinline__ uint32_t ex2h2(uint32_t h) {
    uint32_t r;
    asm("ex2.approx.f16x2 %0, %1;" : "=r"(r) : "r"(h));
    return r;
}

__device__ __forceinline__ void cpasync16(uint32_t dst, const void* src) {
    asm volatile("cp.async.cg.shared.global [%0], [%1], 16;" :: "r"(dst), "l"(src));
}
#define CP_COMMIT() asm volatile("cp.async.commit_group;" ::: "memory")

// ============================================================================
// Kernel 0: weight prep — qkv W image (scales folded) AND wo image + biases.
// ============================================================================
__global__ __launch_bounds__(512) void prep_kernel(
    const float* __restrict__ wq, const float* __restrict__ bq,
    const float* __restrict__ wk, const float* __restrict__ bk,
    const float* __restrict__ wv, const float* __restrict__ bv,
    const float* __restrict__ wo, const float* __restrict__ bo)
{
    const int i = blockIdx.x * 512 + threadIdx.x;
    if (i < 6144) {
        int row = i >> 5, c2 = i & 31;
        const float* wsrc = (row < 64) ? wq : (row < 128) ? wk : wv;
        int r = row & 63;
        float w0 = wsrc[r * 64 + 2 * c2], w1 = wsrc[r * 64 + 2 * c2 + 1];
        if (row < 64) { w0 *= QSCALE; w1 *= QSCALE; }
        __half2 h = __floats2half2_rn(w0, w1);
        g_W16[row * 36 + c2] = *(uint32_t*)&h;
    }
    if (i < 2048) {
        int row = i >> 5, c2 = i & 31;
        __half2 h = __floats2half2_rn(wo[row * 64 + 2 * c2],
                                      wo[row * 64 + 2 * c2 + 1]);
        g_WO16[row * 36 + c2] = *(uint32_t*)&h;
    }
    if (i < 192) {
        g_B[i] = (i < 64) ? bq[i] * QSCALE
               : (i < 128) ? bk[i - 64] : bv[i - 128];
    }
    if (i < 64) g_BO[i] = bo[i];
}

// ============================================================================
// Kernel A: fused QKV projection via mma.sync f16 (round-15 version verbatim).
// ============================================================================
#define WS_OFF  0
#define XS_OFF  6912
#define QST_OFF 9216
#define KST_OFF 11520
#define VST_OFF 13824
#define BS_OFF  16128
#define QKV_SMEM_BYTES ((16128 + 192) * 4)   // 65,280 B

__global__ __launch_bounds__(128, 3) void qkv_kernel(const float* __restrict__ x)
{
    extern __shared__ uint32_t smw[];
    uint32_t* xs  = smw + XS_OFF;               // [64][36]
    __half*  qst  = (__half*)(smw + QST_OFF);   // [64][72]
    __half*  kst  = (__half*)(smw + KST_OFF);   // [64][72]
    __half*  vst  = (__half*)(smw + VST_OFF);   // [64 chan][72 pos]
    float*   bs   = (float*)(smw + BS_OFF);     // [192]
    const uint32_t sbase = smem_u32(smw);

    const int tid  = threadIdx.x;
    const int wid  = tid >> 5, lane = tid & 31;
    const int g    = lane >> 2, tig = lane & 3;
    const int b    = blockIdx.y;
    const int n0   = blockIdx.x * 64;
    const int p0   = wid * 16;

    for (int i = tid; i < 1728; i += 128)
        cpasync16(sbase + (uint32_t)(i * 16), (const uint4*)g_W16 + i);
    if (tid < 48)
        cpasync16(sbase + (uint32_t)(BS_OFF * 4 + tid * 16), (const uint4*)g_B + tid);
    CP_COMMIT();

    for (int i = tid; i < 2048; i += 128) {
        int c2 = i >> 6, p = i & 63;
        float x0 = x[(b * 64 + 2 * c2    ) * NPOS + n0 + p];
        float x1 = x[(b * 64 + 2 * c2 + 1) * NPOS + n0 + p];
        __half2 h = __floats2half2_rn(x0, x1);
        xs[p * 36 + c2] = *(uint32_t*)&h;
    }
    asm volatile("cp.async.wait_group 0;" ::: "memory");
    __syncthreads();

    const int row_in = (lane & 7) | ((lane >> 4) << 3);
    const int woff   = ((lane >> 3) & 1) << 2;
    const uint32_t xLane = sbase + (uint32_t)((XS_OFF + (p0 + row_in) * 36 + woff) * 4);
    uint32_t bfr[4][4];
#pragma unroll
    for (int kk = 0; kk < 4; ++kk)
        ldsm4(bfr[kk][0], bfr[kk][1], bfr[kk][2], bfr[kk][3],
              xLane + (uint32_t)(kk * 32));

    const uint32_t aLaneBase = sbase
        + (uint32_t)(((lane & 15) * 36) * 4) + (uint32_t)(((lane >> 4) << 4));

    const int pA = p0 + 2 * tig;
    const int pB = pA + 8;

#pragma unroll
    for (int mb = 0; mb < 12; ++mb) {
        float d0[4] = {0.f, 0.f, 0.f, 0.f};
        float d1[4] = {0.f, 0.f, 0.f, 0.f};
        const uint32_t aL = aLaneBase + (uint32_t)(mb * 16 * 36 * 4);
#pragma unroll
        for (int kk = 0; kk < 4; ++kk) {
            uint32_t a[4];
            ldsm4(a[0], a[1], a[2], a[3], aL + (uint32_t)(kk * 32));
            mma_f16(d0, a, bfr[kk][0], bfr[kk][1], d0);
            mma_f16(d1, a, bfr[kk][2], bfr[kk][3], d1);
        }
        const int ch0 = mb * 16 + g, ch1 = ch0 + 8;
        const float bb0 = bs[ch0], bb1 = bs[ch1];
        if (mb < 8) {
            __half* st = (mb < 4) ? qst : kst;
            const int cc0 = ch0 & 63, cc1 = ch1 & 63;
            st[ pA      * 72 + cc0] = __float2half_rn(d0[0] + bb0);
            st[(pA + 1) * 72 + cc0] = __float2half_rn(d0[1] + bb0);
            st[ pA      * 72 + cc1] = __float2half_rn(d0[2] + bb1);
            st[(pA + 1) * 72 + cc1] = __float2half_rn(d0[3] + bb1);
            st[ pB      * 72 + cc0] = __float2half_rn(d1[0] + bb0);
            st[(pB + 1) * 72 + cc0] = __float2half_rn(d1[1] + bb0);
            st[ pB      * 72 + cc1] = __float2half_rn(d1[2] + bb1);
            st[(pB + 1) * 72 + cc1] = __float2half_rn(d1[3] + bb1);
        } else {
            const int cc0 = ch0 - 128, cc1 = ch1 - 128;
            *(__half2*)&vst[cc0 * 72 + pA] = __floats2half2_rn(d0[0] + bb0, d0[1] + bb0);
            *(__half2*)&vst[cc1 * 72 + pA] = __floats2half2_rn(d0[2] + bb1, d0[3] + bb1);
            *(__half2*)&vst[cc0 * 72 + pB] = __floats2half2_rn(d1[0] + bb0, d1[1] + bb0);
            *(__half2*)&vst[cc1 * 72 + pB] = __floats2half2_rn(d1[2] + bb1, d1[3] + bb1);
        }
    }
    __syncthreads();

    for (int i = tid; i < 512; i += 128) {
        int r = i >> 3, c8 = (i & 7) << 3;
        *(uint4*)&g_Qh[((b * NPOS) + n0 + r) * 64 + c8] =
            *(const uint4*)&qst[r * 72 + c8];
        *(uint4*)&g_Kh[((b * NPOS) + n0 + r) * 64 + c8] =
            *(const uint4*)&kst[r * 72 + c8];
    }
    for (int i = tid; i < 512; i += 128) {
        int r = i >> 3, p8 = (i & 7) << 3;
        *(uint4*)&g_Vt[((b * 64) + r) * NPOS + n0 + p8] =
            *(const uint4*)&vst[r * 72 + p8];
    }
}

// ============================================================================
// Kernel B: flash attention (round-14 version verbatim; HMMA-rate floor).
// ============================================================================
#define QSTW 36
#define VSTW 132
#define KTILE_B (256 * QSTW * 4)
#define VTILE_B (64 * VSTW * 4)
#define FLASH_SMEM_BYTES (128 * QSTW * 4 + 2 * KTILE_B + 2 * VTILE_B) // 159,744

template<int JMAX>
__device__ __forceinline__ void do_tile(uint32_t kb, uint32_t vb,
                                        const uint32_t qa[4][4],
                                        float ofrag[8][4],
                                        float& lsum0, float& lsum1)
{
    uint32_t sfh[2 * JMAX][2];
#pragma unroll
    for (int nb = 0; nb < 2 * JMAX; ++nb) { sfh[nb][0] = 0u; sfh[nb][1] = 0u; }
#pragma unroll
    for (int k = 0; k < 4; ++k) {
#pragma unroll
        for (int j = 0; j < JMAX; ++j) {
            uint32_t d0, d1, d2, d3;
            ldsm4(d0, d1, d2, d3, kb + (uint32_t)((j * 16 * QSTW + 8 * k) * 4));
            mma_f16h(sfh[2 * j    ], qa[k], d0, d1, sfh[2 * j    ][0], sfh[2 * j    ][1]);
            mma_f16h(sfh[2 * j + 1], qa[k], d2, d3, sfh[2 * j + 1][0], sfh[2 * j + 1][1]);
        }
    }

    uint32_t pa[JMAX][4];
#pragma unroll
    for (int j = 0; j < JMAX; ++j) {
        pa[j][0] = ex2h2(sfh[2 * j    ][0]);
        pa[j][1] = ex2h2(sfh[2 * j    ][1]);
        pa[j][2] = ex2h2(sfh[2 * j + 1][0]);
        pa[j][3] = ex2h2(sfh[2 * j + 1][1]);
    }

    {
        __half2 h0 = __floats2half2_rn(0.f, 0.f);
        __half2 h1 = h0;
#pragma unroll
        for (int j = 0; j < JMAX; ++j) {
            h0 = __hadd2(h0, *(const __half2*)&pa[j][0]);
            h0 = __hadd2(h0, *(const __half2*)&pa[j][2]);
            h1 = __hadd2(h1, *(const __half2*)&pa[j][1]);
            h1 = __hadd2(h1, *(const __half2*)&pa[j][3]);
        }
        lsum0 += __low2float(h0) + __high2float(h0);
        lsum1 += __low2float(h1) + __high2float(h1);
    }

#pragma unroll
    for (int j = 0; j < JMAX; ++j) {
#pragma unroll
        for (int nb2 = 0; nb2 < 4; ++nb2) {
            uint32_t v0, v1, v2, v3;
            ldsm4(v0, v1, v2, v3, vb + (uint32_t)((nb2 * 16 * VSTW + 8 * j) * 4));
            mma_f16(ofrag[2 * nb2    ], pa[j], v0, v1, ofrag[2 * nb2    ]);
            mma_f16(ofrag[2 * nb2 + 1], pa[j], v2, v3, ofrag[2 * nb2 + 1]);
        }
    }
}

__global__ __launch_bounds__(256, 1) void flash_mma_kernel()
{
    extern __shared__ uint32_t smw[];
    uint32_t* Qw = smw;                              // [128][36]
    const uint32_t sbase  = smem_u32(smw);
    const uint32_t kbase0 = sbase + 128 * QSTW * 4;
    const uint32_t vbase0 = kbase0 + 2 * KTILE_B;

    const int tid  = threadIdx.x;
    const int wid  = tid >> 5, lane = tid & 31;
    const int g    = lane >> 2, tig = lane & 3;
    const int b    = blockIdx.x / NCPB;
    const int c    = blockIdx.x % NCPB;
    const int item = c + NCPB * wid;
    const bool valid = (item < NITEMS);
    const int rbase = item * 16;
    const int rb   = wid * 16;

    if (valid) {
#pragma unroll
        for (int i = 0; i < 4; ++i) {
            int idx = lane + 32 * i;
            int rr = idx >> 3, c8 = (idx & 7) << 3;
            uint4 v = *(const uint4*)&g_Qh[((b * NPOS) + rbase + rr) * 64 + c8];
            *(uint4*)&Qw[(rb + rr) * QSTW + (c8 >> 1)] = v;
        }
    }
    __syncthreads();

    uint32_t qa[4][4];
#pragma unroll
    for (int k = 0; k < 4; ++k) {
        qa[k][0] = Qw[(rb + g    ) * QSTW + 8 * k + tig];
        qa[k][1] = Qw[(rb + g + 8) * QSTW + 8 * k + tig];
        qa[k][2] = Qw[(rb + g    ) * QSTW + 8 * k + tig + 4];
        qa[k][3] = Qw[(rb + g + 8) * QSTW + 8 * k + tig + 4];
    }

    const int row_in = (lane & 7) | ((lane >> 4) << 3);
    const int woff   = ((lane >> 3) & 1) << 2;
    const uint32_t kLane = (uint32_t)((row_in * QSTW + woff) * 4);
    const uint32_t vLane = (uint32_t)((row_in * VSTW + woff) * 4);

    float ofrag[8][4];
#pragma unroll
    for (int nb = 0; nb < 8; ++nb)
#pragma unroll
        for (int i = 0; i < 4; ++i) ofrag[nb][i] = 0.f;
    float lsum0 = 0.f, lsum1 = 0.f;

    auto fill_async = [&](int t, uint32_t kdst, uint32_t vdst) {
        const int kv0 = t * 256;
#pragma unroll
        for (int i = 0; i < 8; ++i) {
            int idx = tid + i * 256;
            int r = idx >> 3, c8 = (idx & 7) << 3;
            cpasync16(kdst + (uint32_t)((r * QSTW + (c8 >> 1)) * 4),
                      &g_Kh[((size_t)(b * NPOS) + kv0 + r) * 64 + c8]);
        }
#pragma unroll
        for (int i = 0; i < 8; ++i) {
            int idx = tid + i * 256;
            int cc = idx >> 5, k8 = (idx & 31) << 3;
            cpasync16(vdst + (uint32_t)((cc * VSTW + (k8 >> 1)) * 4),
                      &g_Vt[((size_t)(b * 64) + cc) * NPOS + kv0 + k8]);
        }
    };

    fill_async(0, kbase0, vbase0);
    CP_COMMIT();

#pragma unroll 1
    for (int t = 0; t < NKT; ++t) {
        __syncthreads();
        const int cur = t & 1;
        if (t + 1 < NKT) {
            fill_async(t + 1, kbase0 + (uint32_t)(((t + 1) & 1) * KTILE_B),
                              vbase0 + (uint32_t)(((t + 1) & 1) * VTILE_B));
            CP_COMMIT();
            asm volatile("cp.async.wait_group 1;" ::: "memory");
        } else {
            asm volatile("cp.async.wait_group 0;" ::: "memory");
        }
        __syncthreads();

        if (!valid) continue;

        const uint32_t kb = kbase0 + (uint32_t)(cur * KTILE_B) + kLane;
        const uint32_t vb = vbase0 + (uint32_t)(cur * VTILE_B) + vLane;

        if (t < NKT - 1) {
            do_tile<8>(kb, vb, qa, ofrag, lsum0, lsum1);
            do_tile<8>(kb + (uint32_t)(128 * QSTW * 4), vb + 256u,
                       qa, ofrag, lsum0, lsum1);
        } else {
            do_tile<4>(kb, vb, qa, ofrag, lsum0, lsum1);
        }
    }

    if (!valid) return;

    lsum0 += __shfl_xor_sync(0xffffffffu, lsum0, 1);
    lsum0 += __shfl_xor_sync(0xffffffffu, lsum0, 2);
    lsum1 += __shfl_xor_sync(0xffffffffu, lsum1, 1);
    lsum1 += __shfl_xor_sync(0xffffffffu, lsum1, 2);
    const float inv0 = 1.0f / lsum0;
    const float inv1 = 1.0f / lsum1;

    const int r0 = rbase + g, r1 = rbase + g + 8;
#pragma unroll
    for (int nb = 0; nb < 8; ++nb) {
        *(float2*)&g_O[((b * NPOS) + r0) * 64 + nb * 8 + 2 * tig]
            = make_float2(ofrag[nb][0] * inv0, ofrag[nb][1] * inv0);
        *(float2*)&g_O[((b * NPOS) + r1) * 64 + nb * 8 + 2 * tig]
            = make_float2(ofrag[nb][2] * inv1, ofrag[nb][3] * inv1);
    }
}

// ============================================================================
// Kernel C: output projection via mma.sync f16 (qkv structure, 16 mma/warp).
//   y[b,o,p] = bo[o] + sum_c wo[o,c] * O[b, c*125 + (p>>6), p&63]
//   128 threads, grid (125, 2). wo image via cp.async (overlaps O gather).
//   smem words: wo[64][36] | os[64 pos][36] | bo[64]
// ============================================================================
#define OP_WO_OFF 0
#define OP_OS_OFF 2304
#define OP_BO_OFF 4608
#define OP_SMEM_BYTES ((4608 + 64) * 4)   // 18,688 B

__global__ __launch_bounds__(128) void out_proj_kernel(float* __restrict__ out)
{
    extern __shared__ uint32_t smw[];
    __half* osh = (__half*)(smw + OP_OS_OFF);   // [64 pos][72 half]
    float*  bos = (float*)(smw + OP_BO_OFF);    // [64]
    const uint32_t sbase = smem_u32(smw);

    const int tid  = threadIdx.x;
    const int wid  = tid >> 5, lane = tid & 31;
    const int g    = lane >> 2, tig = lane & 3;
    const int b    = blockIdx.y;
    const int bx   = blockIdx.x;      // position tile: p = bx*64 + pl
    const int p0   = wid * 16;        // this warp's 16 positions

    // ---- wo image + bo via cp.async (576 + 16 uint4) ----
    for (int i = tid; i < 576; i += 128)
        cpasync16(sbase + (uint32_t)(i * 16), (const uint4*)g_WO16 + i);
    if (tid < 16)
        cpasync16(sbase + (uint32_t)(OP_BO_OFF * 4 + tid * 16), (const uint4*)g_BO + tid);
    CP_COMMIT();

    // ---- gather O (reinterpret reshape) -> f16 os[pos][chan] (overlaps) ----
    for (int i = tid; i < 4096; i += 128) {
        int c = i >> 6, p = i & 63;   // consecutive tid -> consecutive p: coalesced
        float v = g_O[((b * NPOS) + c * 125 + bx) * 64 + p];
        osh[p * 72 + c] = __float2half_rn(v);
    }
    asm volatile("cp.async.wait_group 0;" ::: "memory");
    __syncthreads();

    // ---- B-fragments: this warp's 16 positions, all 64 c (4 chunks) ----
    const int row_in = (lane & 7) | ((lane >> 4) << 3);
    const int woff   = ((lane >> 3) & 1) << 2;
    const uint32_t xLane = sbase + (uint32_t)((OP_OS_OFF + (p0 + row_in) * 36 + woff) * 4);
    uint32_t bfr[4][4];
#pragma unroll
    for (int kk = 0; kk < 4; ++kk)
        ldsm4(bfr[kk][0], bfr[kk][1], bfr[kk][2], bfr[kk][3],
              xLane + (uint32_t)(kk * 32));

    const uint32_t aLaneBase = sbase
        + (uint32_t)(((lane & 15) * 36) * 4) + (uint32_t)(((lane >> 4) << 4));

    const int pA = p0 + 2 * tig;
    const int pB = pA + 8;

#pragma unroll
    for (int mb = 0; mb < 4; ++mb) {
        float d0[4] = {0.f, 0.f, 0.f, 0.f};
        float d1[4] = {0.f, 0.f, 0.f, 0.f};
        const uint32_t aL = aLaneBase + (uint32_t)(mb * 16 * 36 * 4);
#pragma unroll
        for (int kk = 0; kk < 4; ++kk) {
            uint32_t a[4];
            ldsm4(a[0], a[1], a[2], a[3], aL + (uint32_t)(kk * 32));
            mma_f16(d0, a, bfr[kk][0], bfr[kk][1], d0);
            mma_f16(d1, a, bfr[kk][2], bfr[kk][3], d1);
        }
        const int ch0 = mb * 16 + g, ch1 = ch0 + 8;
        const float bb0 = bos[ch0], bb1 = bos[ch1];
        float* o0 = &out[((b * 64) + ch0) * NPOS + bx * 64];
        float* o1 = &out[((b * 64) + ch1) * NPOS + bx * 64];
        *(float2*)&o0[pA] = make_float2(d0[0] + bb0, d0[1] + bb0);
        *(float2*)&o1[pA] = make_float2(d0[2] + bb1, d0[3] + bb1);
        *(float2*)&o0[pB] = make_float2(d1[0] + bb0, d1[1] + bb0);
        *(float2*)&o1[pB] = make_float2(d1[2] + bb1, d1[3] + bb1);
    }
}

// ============================================================================
extern "C" void kernel_launch(void* const* d_in, const int* in_sizes, int n_in,
                              void* d_out, int out_size)
{
    (void)in_sizes; (void)n_in; (void)out_size;
    const float* x  = (const float*)d_in[0];
    const float* wq = (const float*)d_in[1];
    const float* bq = (const float*)d_in[2];
    const float* wk = (const float*)d_in[3];
    const float* bk = (const float*)d_in[4];
    const float* wv = (const float*)d_in[5];
    const float* bv = (const float*)d_in[6];
    const float* wo = (const float*)d_in[7];
    const float* bo = (const float*)d_in[8];
    float* out = (float*)d_out;

    cudaFuncSetAttribute(qkv_kernel,
                         cudaFuncAttributeMaxDynamicSharedMemorySize, QKV_SMEM_BYTES);
    cudaFuncSetAttribute(flash_mma_kernel,
                         cudaFuncAttributeMaxDynamicSharedMemorySize, FLASH_SMEM_BYTES);
    cudaFuncSetAttribute(out_proj_kernel,
                         cudaFuncAttributeMaxDynamicSharedMemorySize, OP_SMEM_BYTES);

    prep_kernel<<<12, 512>>>(wq, bq, wk, bk, wv, bv, wo, bo);
    qkv_kernel<<<dim3(125, BATCH), 128, QKV_SMEM_BYTES>>>(x);
    flash_mma_kernel<<<BATCH * NCPB, 256, FLASH_SMEM_BYTES>>>();
    out_proj_kernel<<<dim3(125, BATCH), 128, OP_SMEM_BYTES>>>(out);
}